// round 3
// baseline (speedup 1.0000x reference)
#include <cuda_runtime.h>

// ============================================================================
// EinFFT for GB300 (sm_103a)
//   x (8,4096,768) -> reshape (8,4096,4,192) -> FFT2 over (seq, block) ortho
//   -> complex block MLP (2 layers, ReLU, softshrink) -> IFFT2 -> real
//
// Pipeline:
//   K1 fft_n_fwd   : 4096-pt FFT along seq, per (batch, 4-col group), smem-resident
//   K2 fft4_pack   : 4-pt FFT along block axis + 1/128 ortho scale,
//                    pack into stacked-real GEMM layout A[blk][m][ [Xr|Xi] 384 ]
//   K3 prep_weights: build stacked real weights [[Wr,Wi],[-Wi,Wr]] and biases
//   K4 gemm<1>     : H = relu(A @ W1s + b1s)        (per block, M=32768,K=N=384)
//   K5 gemm<2>     : A = softshrink(H @ W2s + b2s)
//   K6 ifft4_unpack: inverse 4-pt FFT along block axis, back to spectrum layout
//   K7 fft_n_inv   : inverse 4096-pt FFT along seq, * 1/128, write real part
// ============================================================================

#define B_DIM 8
#define N_DIM 4096
#define C_DIM 768
#define BS    192          // block size (bs)
#define NB    4            // NUM_BLOCKS
#define M_TOT (B_DIM * N_DIM)   // 32768 GEMM rows
#define KS    384               // stacked K = N = 2*bs
#define LAMBDA 0.01f
#define INV128 (1.0f / 128.0f)  // 1/sqrt(4096*4)

// -------- scratch (static device globals; no allocation allowed) ------------
static __device__ float g_Fr[(size_t)B_DIM * N_DIM * C_DIM];
static __device__ float g_Fi[(size_t)B_DIM * N_DIM * C_DIM];
static __device__ float g_A [(size_t)NB * M_TOT * KS];
static __device__ float g_H [(size_t)NB * M_TOT * KS];
static __device__ float g_W1[NB * KS * KS];
static __device__ float g_W2[NB * KS * KS];
static __device__ float g_B1[NB * KS];
static __device__ float g_B2[NB * KS];

// ============================================================================
// K1: forward FFT-4096 along seq axis. One CTA = one batch x 4 adjacent
// channels. Radix-2 DIT, bit-reversed load, in shared memory.
// Dynamic smem: 4 cols * 4096 * (re+im) * 4B = 128 KB.
// ============================================================================
__global__ void fft_n_fwd(const float* __restrict__ x) {
    extern __shared__ float sm[];
    float* sr = sm;
    float* si = sm + 4 * N_DIM;

    const int b  = blockIdx.x / (C_DIM / 4);
    const int c0 = (blockIdx.x % (C_DIM / 4)) * 4;
    const int tid = threadIdx.x;

    // load (bit-reversed positions), imag = 0
    for (int n = tid; n < N_DIM; n += blockDim.x) {
        float4 v = *(const float4*)&x[((size_t)(b * N_DIM + n)) * C_DIM + c0];
        int r = __brev((unsigned)n) >> 20;   // 12-bit reversal
        sr[0 * N_DIM + r] = v.x;  sr[1 * N_DIM + r] = v.y;
        sr[2 * N_DIM + r] = v.z;  sr[3 * N_DIM + r] = v.w;
        si[0 * N_DIM + r] = 0.f;  si[1 * N_DIM + r] = 0.f;
        si[2 * N_DIM + r] = 0.f;  si[3 * N_DIM + r] = 0.f;
    }
    __syncthreads();

    for (int len = 2; len <= N_DIM; len <<= 1) {
        const int half = len >> 1;
        const float ang0 = -6.283185307179586f / (float)len;
        for (int idx = tid; idx < 4 * (N_DIM / 2); idx += blockDim.x) {
            const int col = idx >> 11;            // N_DIM/2 = 2048 = 1<<11
            const int j   = idx & (N_DIM / 2 - 1);
            const int pos = j & (half - 1);
            const int i0  = ((j - pos) << 1) + pos;
            const int i1  = i0 + half;
            float s, c;
            __sincosf(ang0 * (float)pos, &s, &c);
            float* pr = sr + col * N_DIM;
            float* pi = si + col * N_DIM;
            float xr = pr[i1], xi = pi[i1];
            float vr = xr * c - xi * s;
            float vi = xr * s + xi * c;
            float ur = pr[i0], ui = pi[i0];
            pr[i0] = ur + vr;  pi[i0] = ui + vi;
            pr[i1] = ur - vr;  pi[i1] = ui - vi;
        }
        __syncthreads();
    }

    for (int k = tid; k < N_DIM; k += blockDim.x) {
        size_t o = ((size_t)(b * N_DIM + k)) * C_DIM + c0;
        float4 vr = make_float4(sr[0 * N_DIM + k], sr[1 * N_DIM + k],
                                sr[2 * N_DIM + k], sr[3 * N_DIM + k]);
        float4 vi = make_float4(si[0 * N_DIM + k], si[1 * N_DIM + k],
                                si[2 * N_DIM + k], si[3 * N_DIM + k]);
        *(float4*)&g_Fr[o] = vr;
        *(float4*)&g_Fi[o] = vi;
    }
}

// ============================================================================
// K2: 4-point FFT along block axis + 1/128 scale, pack to GEMM layout:
//   A[k2][m][d]      = Re, A[k2][m][192+d] = Im,  A plane stride = M_TOT*KS
// ============================================================================
__global__ void fft4_pack() {
    int idx = blockIdx.x * blockDim.x + threadIdx.x;
    if (idx >= M_TOT * BS) return;
    const int m = idx / BS;
    const int d = idx % BS;

    const size_t base = (size_t)m * C_DIM + d;
    float xr0 = g_Fr[base],          xi0 = g_Fi[base];
    float xr1 = g_Fr[base + BS],     xi1 = g_Fi[base + BS];
    float xr2 = g_Fr[base + 2 * BS], xi2 = g_Fi[base + 2 * BS];
    float xr3 = g_Fr[base + 3 * BS], xi3 = g_Fi[base + 3 * BS];

    // X[k2] = sum_j x[j] * e^{-2 pi i j k2 / 4}
    float yr0 = (xr0 + xr1 + xr2 + xr3) * INV128;
    float yi0 = (xi0 + xi1 + xi2 + xi3) * INV128;
    float yr1 = (xr0 + xi1 - xr2 - xi3) * INV128;
    float yi1 = (xi0 - xr1 - xi2 + xr3) * INV128;
    float yr2 = (xr0 - xr1 + xr2 - xr3) * INV128;
    float yi2 = (xi0 - xi1 + xi2 - xi3) * INV128;
    float yr3 = (xr0 - xi1 - xr2 + xi3) * INV128;
    float yi3 = (xi0 + xr1 - xi2 - xr3) * INV128;

    const size_t PL = (size_t)M_TOT * KS;
    const size_t p  = (size_t)m * KS + d;
    g_A[p]               = yr0;  g_A[p + BS]               = yi0;
    g_A[p + PL]          = yr1;  g_A[p + PL + BS]          = yi1;
    g_A[p + 2 * PL]      = yr2;  g_A[p + 2 * PL + BS]      = yi2;
    g_A[p + 3 * PL]      = yr3;  g_A[p + 3 * PL + BS]      = yi3;
}

// ============================================================================
// K3: stacked real weights.  Ws = [[Wr, Wi], [-Wi, Wr]]  (row = input d-stack,
// col = output k-stack).  Inputs: (2, NB, 192, 192) and (2, NB, 192).
// ============================================================================
__global__ void prep_weights(const float* __restrict__ w1,
                             const float* __restrict__ b1,
                             const float* __restrict__ w2,
                             const float* __restrict__ b2) {
    int idx = blockIdx.x * blockDim.x + threadIdx.x;
    if (idx < NB * KS * KS) {
        int col = idx % KS;
        int row = (idx / KS) % KS;
        int blk = idx / (KS * KS);
        int dd = (row < BS) ? row : row - BS;
        int kk = (col < BS) ? col : col - BS;
        size_t ir = ((size_t)(0 * NB + blk) * BS + dd) * BS + kk;  // real part
        size_t ii = ((size_t)(1 * NB + blk) * BS + dd) * BS + kk;  // imag part
        bool rlo = row < BS, clo = col < BS;
        float v1, v2;
        if (rlo == clo)      { v1 =  w1[ir]; v2 =  w2[ir]; }   // Wr diag blocks
        else if (rlo)        { v1 =  w1[ii]; v2 =  w2[ii]; }   // top-right: Wi
        else                 { v1 = -w1[ii]; v2 = -w2[ii]; }   // bot-left: -Wi
        g_W1[idx] = v1;
        g_W2[idx] = v2;
    }
    if (idx < NB * KS) {
        int blk = idx / KS;
        int c   = idx % KS;
        size_t ib = (c < BS) ? ((size_t)(0 * NB + blk) * BS + c)
                             : ((size_t)(1 * NB + blk) * BS + (c - BS));
        g_B1[idx] = b1[ib];
        g_B2[idx] = b2[ib];
    }
}

// ============================================================================
// K4/K5: fp32 SGEMM + bias + activation.
//   LAYER 1: H = relu(A @ W1 + b1);  LAYER 2: A = softshrink(H @ W2 + b2)
// Tiles 128x128x16, 256 threads, 8x8 register blocking.
// ============================================================================
template <int LAYER>
__global__ __launch_bounds__(256, 2) void gemm_act() {
    const float* __restrict__ Ag = (LAYER == 1) ? g_A  : g_H;
    const float* __restrict__ Wg = (LAYER == 1) ? g_W1 : g_W2;
    const float* __restrict__ bg = (LAYER == 1) ? g_B1 : g_B2;
    float* __restrict__ Cg       = (LAYER == 1) ? g_H  : g_A;

    const int blk = blockIdx.z;
    const float* A    = Ag + (size_t)blk * M_TOT * KS;
    const float* W    = Wg + (size_t)blk * KS * KS;
    const float* bias = bg + blk * KS;
    float* C          = Cg + (size_t)blk * M_TOT * KS;

    const int tile_n = blockIdx.x * 128;
    const int tile_m = blockIdx.y * 128;
    const int tid = threadIdx.x;

    __shared__ float As[16][132];   // +4 pad: float4-aligned, fewer ST conflicts
    __shared__ float Bs[16][128];

    const int tm = (tid / 16) * 8;
    const int tn = (tid % 16) * 8;

    // loader indices
    const int a_r = tid >> 2;            // 0..63
    const int a_k = (tid & 3) * 4;       // 0,4,8,12
    const int b_r = tid >> 5;            // 0..7
    const int b_c = (tid & 31) * 4;      // 0..124

    float acc[8][8] = {};

    for (int k0 = 0; k0 < KS; k0 += 16) {
        float4 av0 = *(const float4*)&A[(size_t)(tile_m + a_r)      * KS + k0 + a_k];
        float4 av1 = *(const float4*)&A[(size_t)(tile_m + a_r + 64) * KS + k0 + a_k];
        float4 bv0 = *(const float4*)&W[(k0 + b_r)     * KS + tile_n + b_c];
        float4 bv1 = *(const float4*)&W[(k0 + b_r + 8) * KS + tile_n + b_c];
        __syncthreads();
        As[a_k + 0][a_r] = av0.x;  As[a_k + 1][a_r] = av0.y;
        As[a_k + 2][a_r] = av0.z;  As[a_k + 3][a_r] = av0.w;
        As[a_k + 0][a_r + 64] = av1.x;  As[a_k + 1][a_r + 64] = av1.y;
        As[a_k + 2][a_r + 64] = av1.z;  As[a_k + 3][a_r + 64] = av1.w;
        *(float4*)&Bs[b_r][b_c]     = bv0;
        *(float4*)&Bs[b_r + 8][b_c] = bv1;
        __syncthreads();

        #pragma unroll
        for (int kk = 0; kk < 16; kk++) {
            float ra[8], rb[8];
            *(float4*)&ra[0] = *(const float4*)&As[kk][tm];
            *(float4*)&ra[4] = *(const float4*)&As[kk][tm + 4];
            *(float4*)&rb[0] = *(const float4*)&Bs[kk][tn];
            *(float4*)&rb[4] = *(const float4*)&Bs[kk][tn + 4];
            #pragma unroll
            for (int i = 0; i < 8; i++)
                #pragma unroll
                for (int j = 0; j < 8; j++)
                    acc[i][j] = fmaf(ra[i], rb[j], acc[i][j]);
        }
    }

    float bv[8];
    #pragma unroll
    for (int j = 0; j < 8; j++) bv[j] = bias[tile_n + tn + j];

    #pragma unroll
    for (int i = 0; i < 8; i++) {
        float o[8];
        #pragma unroll
        for (int j = 0; j < 8; j++) {
            float v = acc[i][j] + bv[j];
            if (LAYER == 1) {
                v = fmaxf(v, 0.f);                              // relu
            } else {
                v = (v > LAMBDA) ? v - LAMBDA
                                 : ((v < -LAMBDA) ? v + LAMBDA : 0.f);  // softshrink
            }
            o[j] = v;
        }
        size_t row = (size_t)(tile_m + tm + i);
        *(float4*)&C[row * KS + tile_n + tn]     = *(float4*)&o[0];
        *(float4*)&C[row * KS + tile_n + tn + 4] = *(float4*)&o[4];
    }
}

// ============================================================================
// K6: inverse 4-point FFT along block axis (unnormalized), back to spectrum.
// ============================================================================
__global__ void ifft4_unpack() {
    int idx = blockIdx.x * blockDim.x + threadIdx.x;
    if (idx >= M_TOT * BS) return;
    const int m = idx / BS;
    const int d = idx % BS;

    const size_t PL = (size_t)M_TOT * KS;
    const size_t p  = (size_t)m * KS + d;
    float yr0 = g_A[p],           yi0 = g_A[p + BS];
    float yr1 = g_A[p + PL],      yi1 = g_A[p + PL + BS];
    float yr2 = g_A[p + 2 * PL],  yi2 = g_A[p + 2 * PL + BS];
    float yr3 = g_A[p + 3 * PL],  yi3 = g_A[p + 3 * PL + BS];

    // z[j] = sum_k Y[k] * e^{+2 pi i j k / 4}
    float zr0 = yr0 + yr1 + yr2 + yr3;
    float zi0 = yi0 + yi1 + yi2 + yi3;
    float zr1 = yr0 - yi1 - yr2 + yi3;
    float zi1 = yi0 + yr1 - yi2 - yr3;
    float zr2 = yr0 - yr1 + yr2 - yr3;
    float zi2 = yi0 - yi1 + yi2 - yi3;
    float zr3 = yr0 + yi1 - yr2 - yi3;
    float zi3 = yi0 - yr1 - yi2 + yr3;

    const size_t base = (size_t)m * C_DIM + d;
    g_Fr[base]          = zr0;  g_Fi[base]          = zi0;
    g_Fr[base + BS]     = zr1;  g_Fi[base + BS]     = zi1;
    g_Fr[base + 2 * BS] = zr2;  g_Fi[base + 2 * BS] = zi2;
    g_Fr[base + 3 * BS] = zr3;  g_Fi[base + 3 * BS] = zi3;
}

// ============================================================================
// K7: inverse FFT-4096 along seq (unnormalized) then * 1/128, real part out.
// ============================================================================
__global__ void fft_n_inv(float* __restrict__ out) {
    extern __shared__ float sm[];
    float* sr = sm;
    float* si = sm + 4 * N_DIM;

    const int b  = blockIdx.x / (C_DIM / 4);
    const int c0 = (blockIdx.x % (C_DIM / 4)) * 4;
    const int tid = threadIdx.x;

    for (int n = tid; n < N_DIM; n += blockDim.x) {
        size_t o = ((size_t)(b * N_DIM + n)) * C_DIM + c0;
        float4 vr = *(const float4*)&g_Fr[o];
        float4 vi = *(const float4*)&g_Fi[o];
        int r = __brev((unsigned)n) >> 20;
        sr[0 * N_DIM + r] = vr.x;  sr[1 * N_DIM + r] = vr.y;
        sr[2 * N_DIM + r] = vr.z;  sr[3 * N_DIM + r] = vr.w;
        si[0 * N_DIM + r] = vi.x;  si[1 * N_DIM + r] = vi.y;
        si[2 * N_DIM + r] = vi.z;  si[3 * N_DIM + r] = vi.w;
    }
    __syncthreads();

    for (int len = 2; len <= N_DIM; len <<= 1) {
        const int half = len >> 1;
        const float ang0 = 6.283185307179586f / (float)len;   // +: inverse
        for (int idx = tid; idx < 4 * (N_DIM / 2); idx += blockDim.x) {
            const int col = idx >> 11;
            const int j   = idx & (N_DIM / 2 - 1);
            const int pos = j & (half - 1);
            const int i0  = ((j - pos) << 1) + pos;
            const int i1  = i0 + half;
            float s, c;
            __sincosf(ang0 * (float)pos, &s, &c);
            float* pr = sr + col * N_DIM;
            float* pi = si + col * N_DIM;
            float xr = pr[i1], xi = pi[i1];
            float vr = xr * c - xi * s;
            float vi = xr * s + xi * c;
            float ur = pr[i0], ui = pi[i0];
            pr[i0] = ur + vr;  pi[i0] = ui + vi;
            pr[i1] = ur - vr;  pi[i1] = ui - vi;
        }
        __syncthreads();
    }

    for (int n = tid; n < N_DIM; n += blockDim.x) {
        float4 o = make_float4(sr[0 * N_DIM + n] * INV128,
                               sr[1 * N_DIM + n] * INV128,
                               sr[2 * N_DIM + n] * INV128,
                               sr[3 * N_DIM + n] * INV128);
        *(float4*)&out[((size_t)(b * N_DIM + n)) * C_DIM + c0] = o;
    }
}

// ============================================================================
// launch
// ============================================================================
extern "C" void kernel_launch(void* const* d_in, const int* in_sizes, int n_in,
                              void* d_out, int out_size) {
    (void)in_sizes; (void)n_in; (void)out_size;
    const float* x  = (const float*)d_in[0];
    const float* w1 = (const float*)d_in[1];
    const float* b1 = (const float*)d_in[2];
    const float* w2 = (const float*)d_in[3];
    const float* b2 = (const float*)d_in[4];
    float* out = (float*)d_out;

    const int FFT_SMEM = 4 * N_DIM * 2 * (int)sizeof(float);   // 131072
    cudaFuncSetAttribute(fft_n_fwd, cudaFuncAttributeMaxDynamicSharedMemorySize, FFT_SMEM);
    cudaFuncSetAttribute(fft_n_inv, cudaFuncAttributeMaxDynamicSharedMemorySize, FFT_SMEM);

    // K1: forward FFT along seq
    fft_n_fwd<<<B_DIM * (C_DIM / 4), 512, FFT_SMEM>>>(x);

    // K2: FFT-4 + ortho scale + pack
    fft4_pack<<<(M_TOT * BS) / 256, 256>>>();

    // K3: stacked weights
    prep_weights<<<(NB * KS * KS + 255) / 256, 256>>>(w1, b1, w2, b2);

    // K4/K5: MLP GEMMs
    dim3 gg(KS / 128, M_TOT / 128, NB);
    gemm_act<1><<<gg, 256>>>();
    gemm_act<2><<<gg, 256>>>();

    // K6: inverse FFT-4
    ifft4_unpack<<<(M_TOT * BS) / 256, 256>>>();

    // K7: inverse FFT along seq + real output
    fft_n_inv<<<B_DIM * (C_DIM / 4), 512, FFT_SMEM>>>(out);
}

// round 4
// speedup vs baseline: 1.0031x; 1.0031x over previous
#include <cuda_runtime.h>

// ============================================================================
// EinFFT for GB300 (sm_103a)
//   x (8,4096,768) -> reshape (8,4096,4,192) -> FFT2 over (seq, block) ortho
//   -> complex block MLP (2 layers, ReLU, softshrink) -> IFFT2 -> real
//
// Pipeline:
//   K1 fft_n_fwd   : 4096-pt FFT along seq, per (batch, 4-col group), smem-resident
//   K2 fft4_pack   : 4-pt FFT along block axis + 1/128 ortho scale,
//                    pack into stacked-real GEMM layout A[blk][m][ [Xr|Xi] 384 ]
//   K3 prep_weights: build stacked real weights [[Wr,Wi],[-Wi,Wr]] and biases
//   K4 gemm<1>     : H = relu(A @ W1s + b1s)        (per block, M=32768,K=N=384)
//   K5 gemm<2>     : A = softshrink(H @ W2s + b2s)
//   K6 ifft4_unpack: inverse 4-pt FFT along block axis, back to spectrum layout
//   K7 fft_n_inv   : inverse 4096-pt FFT along seq, * 1/128, write real part
// ============================================================================

#define B_DIM 8
#define N_DIM 4096
#define C_DIM 768
#define BS    192          // block size (bs)
#define NB    4            // NUM_BLOCKS
#define M_TOT (B_DIM * N_DIM)   // 32768 GEMM rows
#define KS    384               // stacked K = N = 2*bs
#define LAMBDA 0.01f
#define INV128 (1.0f / 128.0f)  // 1/sqrt(4096*4)

// -------- scratch (static device globals; no allocation allowed) ------------
static __device__ float g_Fr[(size_t)B_DIM * N_DIM * C_DIM];
static __device__ float g_Fi[(size_t)B_DIM * N_DIM * C_DIM];
static __device__ float g_A [(size_t)NB * M_TOT * KS];
static __device__ float g_H [(size_t)NB * M_TOT * KS];
static __device__ float g_W1[NB * KS * KS];
static __device__ float g_W2[NB * KS * KS];
static __device__ float g_B1[NB * KS];
static __device__ float g_B2[NB * KS];

// ============================================================================
// K1: forward FFT-4096 along seq axis. One CTA = one batch x 4 adjacent
// channels. Radix-2 DIT, bit-reversed load, in shared memory.
// Dynamic smem: 4 cols * 4096 * (re+im) * 4B = 128 KB.
// ============================================================================
__global__ void fft_n_fwd(const float* __restrict__ x) {
    extern __shared__ float sm[];
    float* sr = sm;
    float* si = sm + 4 * N_DIM;

    const int b  = blockIdx.x / (C_DIM / 4);
    const int c0 = (blockIdx.x % (C_DIM / 4)) * 4;
    const int tid = threadIdx.x;

    // load (bit-reversed positions), imag = 0
    for (int n = tid; n < N_DIM; n += blockDim.x) {
        float4 v = *(const float4*)&x[((size_t)(b * N_DIM + n)) * C_DIM + c0];
        int r = __brev((unsigned)n) >> 20;   // 12-bit reversal
        sr[0 * N_DIM + r] = v.x;  sr[1 * N_DIM + r] = v.y;
        sr[2 * N_DIM + r] = v.z;  sr[3 * N_DIM + r] = v.w;
        si[0 * N_DIM + r] = 0.f;  si[1 * N_DIM + r] = 0.f;
        si[2 * N_DIM + r] = 0.f;  si[3 * N_DIM + r] = 0.f;
    }
    __syncthreads();

    for (int len = 2; len <= N_DIM; len <<= 1) {
        const int half = len >> 1;
        const float ang0 = -6.283185307179586f / (float)len;
        for (int idx = tid; idx < 4 * (N_DIM / 2); idx += blockDim.x) {
            const int col = idx >> 11;            // N_DIM/2 = 2048 = 1<<11
            const int j   = idx & (N_DIM / 2 - 1);
            const int pos = j & (half - 1);
            const int i0  = ((j - pos) << 1) + pos;
            const int i1  = i0 + half;
            float s, c;
            __sincosf(ang0 * (float)pos, &s, &c);
            float* pr = sr + col * N_DIM;
            float* pi = si + col * N_DIM;
            float xr = pr[i1], xi = pi[i1];
            float vr = xr * c - xi * s;
            float vi = xr * s + xi * c;
            float ur = pr[i0], ui = pi[i0];
            pr[i0] = ur + vr;  pi[i0] = ui + vi;
            pr[i1] = ur - vr;  pi[i1] = ui - vi;
        }
        __syncthreads();
    }

    for (int k = tid; k < N_DIM; k += blockDim.x) {
        size_t o = ((size_t)(b * N_DIM + k)) * C_DIM + c0;
        float4 vr = make_float4(sr[0 * N_DIM + k], sr[1 * N_DIM + k],
                                sr[2 * N_DIM + k], sr[3 * N_DIM + k]);
        float4 vi = make_float4(si[0 * N_DIM + k], si[1 * N_DIM + k],
                                si[2 * N_DIM + k], si[3 * N_DIM + k]);
        *(float4*)&g_Fr[o] = vr;
        *(float4*)&g_Fi[o] = vi;
    }
}

// ============================================================================
// K2: 4-point FFT along block axis + 1/128 scale, pack to GEMM layout:
//   A[k2][m][d]      = Re, A[k2][m][192+d] = Im,  A plane stride = M_TOT*KS
// ============================================================================
__global__ void fft4_pack() {
    int idx = blockIdx.x * blockDim.x + threadIdx.x;
    if (idx >= M_TOT * BS) return;
    const int m = idx / BS;
    const int d = idx % BS;

    const size_t base = (size_t)m * C_DIM + d;
    float xr0 = g_Fr[base],          xi0 = g_Fi[base];
    float xr1 = g_Fr[base + BS],     xi1 = g_Fi[base + BS];
    float xr2 = g_Fr[base + 2 * BS], xi2 = g_Fi[base + 2 * BS];
    float xr3 = g_Fr[base + 3 * BS], xi3 = g_Fi[base + 3 * BS];

    // X[k2] = sum_j x[j] * e^{-2 pi i j k2 / 4}
    float yr0 = (xr0 + xr1 + xr2 + xr3) * INV128;
    float yi0 = (xi0 + xi1 + xi2 + xi3) * INV128;
    float yr1 = (xr0 + xi1 - xr2 - xi3) * INV128;
    float yi1 = (xi0 - xr1 - xi2 + xr3) * INV128;
    float yr2 = (xr0 - xr1 + xr2 - xr3) * INV128;
    float yi2 = (xi0 - xi1 + xi2 - xi3) * INV128;
    float yr3 = (xr0 - xi1 - xr2 + xi3) * INV128;
    float yi3 = (xi0 + xr1 - xi2 - xr3) * INV128;

    const size_t PL = (size_t)M_TOT * KS;
    const size_t p  = (size_t)m * KS + d;
    g_A[p]               = yr0;  g_A[p + BS]               = yi0;
    g_A[p + PL]          = yr1;  g_A[p + PL + BS]          = yi1;
    g_A[p + 2 * PL]      = yr2;  g_A[p + 2 * PL + BS]      = yi2;
    g_A[p + 3 * PL]      = yr3;  g_A[p + 3 * PL + BS]      = yi3;
}

// ============================================================================
// K3: stacked real weights.  Ws = [[Wr, Wi], [-Wi, Wr]]  (row = input d-stack,
// col = output k-stack).  Inputs: (2, NB, 192, 192) and (2, NB, 192).
// ============================================================================
__global__ void prep_weights(const float* __restrict__ w1,
                             const float* __restrict__ b1,
                             const float* __restrict__ w2,
                             const float* __restrict__ b2) {
    int idx = blockIdx.x * blockDim.x + threadIdx.x;
    if (idx < NB * KS * KS) {
        int col = idx % KS;
        int row = (idx / KS) % KS;
        int blk = idx / (KS * KS);
        int dd = (row < BS) ? row : row - BS;
        int kk = (col < BS) ? col : col - BS;
        size_t ir = ((size_t)(0 * NB + blk) * BS + dd) * BS + kk;  // real part
        size_t ii = ((size_t)(1 * NB + blk) * BS + dd) * BS + kk;  // imag part
        bool rlo = row < BS, clo = col < BS;
        float v1, v2;
        if (rlo == clo)      { v1 =  w1[ir]; v2 =  w2[ir]; }   // Wr diag blocks
        else if (rlo)        { v1 =  w1[ii]; v2 =  w2[ii]; }   // top-right: Wi
        else                 { v1 = -w1[ii]; v2 = -w2[ii]; }   // bot-left: -Wi
        g_W1[idx] = v1;
        g_W2[idx] = v2;
    }
    if (idx < NB * KS) {
        int blk = idx / KS;
        int c   = idx % KS;
        size_t ib = (c < BS) ? ((size_t)(0 * NB + blk) * BS + c)
                             : ((size_t)(1 * NB + blk) * BS + (c - BS));
        g_B1[idx] = b1[ib];
        g_B2[idx] = b2[ib];
    }
}

// ============================================================================
// K4/K5: fp32 SGEMM + bias + activation.
//   LAYER 1: H = relu(A @ W1 + b1);  LAYER 2: A = softshrink(H @ W2 + b2)
// Tiles 128x128x16, 256 threads, 8x8 register blocking.
// ============================================================================
template <int LAYER>
__global__ __launch_bounds__(256, 2) void gemm_act() {
    const float* __restrict__ Ag = (LAYER == 1) ? g_A  : g_H;
    const float* __restrict__ Wg = (LAYER == 1) ? g_W1 : g_W2;
    const float* __restrict__ bg = (LAYER == 1) ? g_B1 : g_B2;
    float* __restrict__ Cg       = (LAYER == 1) ? g_H  : g_A;

    const int blk = blockIdx.z;
    const float* A    = Ag + (size_t)blk * M_TOT * KS;
    const float* W    = Wg + (size_t)blk * KS * KS;
    const float* bias = bg + blk * KS;
    float* C          = Cg + (size_t)blk * M_TOT * KS;

    const int tile_n = blockIdx.x * 128;
    const int tile_m = blockIdx.y * 128;
    const int tid = threadIdx.x;

    __shared__ float As[16][132];   // +4 pad: float4-aligned, fewer ST conflicts
    __shared__ float Bs[16][128];

    const int tm = (tid / 16) * 8;
    const int tn = (tid % 16) * 8;

    // loader indices
    const int a_r = tid >> 2;            // 0..63
    const int a_k = (tid & 3) * 4;       // 0,4,8,12
    const int b_r = tid >> 5;            // 0..7
    const int b_c = (tid & 31) * 4;      // 0..124

    float acc[8][8] = {};

    for (int k0 = 0; k0 < KS; k0 += 16) {
        float4 av0 = *(const float4*)&A[(size_t)(tile_m + a_r)      * KS + k0 + a_k];
        float4 av1 = *(const float4*)&A[(size_t)(tile_m + a_r + 64) * KS + k0 + a_k];
        float4 bv0 = *(const float4*)&W[(k0 + b_r)     * KS + tile_n + b_c];
        float4 bv1 = *(const float4*)&W[(k0 + b_r + 8) * KS + tile_n + b_c];
        __syncthreads();
        As[a_k + 0][a_r] = av0.x;  As[a_k + 1][a_r] = av0.y;
        As[a_k + 2][a_r] = av0.z;  As[a_k + 3][a_r] = av0.w;
        As[a_k + 0][a_r + 64] = av1.x;  As[a_k + 1][a_r + 64] = av1.y;
        As[a_k + 2][a_r + 64] = av1.z;  As[a_k + 3][a_r + 64] = av1.w;
        *(float4*)&Bs[b_r][b_c]     = bv0;
        *(float4*)&Bs[b_r + 8][b_c] = bv1;
        __syncthreads();

        #pragma unroll
        for (int kk = 0; kk < 16; kk++) {
            float ra[8], rb[8];
            *(float4*)&ra[0] = *(const float4*)&As[kk][tm];
            *(float4*)&ra[4] = *(const float4*)&As[kk][tm + 4];
            *(float4*)&rb[0] = *(const float4*)&Bs[kk][tn];
            *(float4*)&rb[4] = *(const float4*)&Bs[kk][tn + 4];
            #pragma unroll
            for (int i = 0; i < 8; i++)
                #pragma unroll
                for (int j = 0; j < 8; j++)
                    acc[i][j] = fmaf(ra[i], rb[j], acc[i][j]);
        }
    }

    float bv[8];
    #pragma unroll
    for (int j = 0; j < 8; j++) bv[j] = bias[tile_n + tn + j];

    #pragma unroll
    for (int i = 0; i < 8; i++) {
        float o[8];
        #pragma unroll
        for (int j = 0; j < 8; j++) {
            float v = acc[i][j] + bv[j];
            if (LAYER == 1) {
                v = fmaxf(v, 0.f);                              // relu
            } else {
                v = (v > LAMBDA) ? v - LAMBDA
                                 : ((v < -LAMBDA) ? v + LAMBDA : 0.f);  // softshrink
            }
            o[j] = v;
        }
        size_t row = (size_t)(tile_m + tm + i);
        *(float4*)&C[row * KS + tile_n + tn]     = *(float4*)&o[0];
        *(float4*)&C[row * KS + tile_n + tn + 4] = *(float4*)&o[4];
    }
}

// ============================================================================
// K6: inverse 4-point FFT along block axis (unnormalized), back to spectrum.
// ============================================================================
__global__ void ifft4_unpack() {
    int idx = blockIdx.x * blockDim.x + threadIdx.x;
    if (idx >= M_TOT * BS) return;
    const int m = idx / BS;
    const int d = idx % BS;

    const size_t PL = (size_t)M_TOT * KS;
    const size_t p  = (size_t)m * KS + d;
    float yr0 = g_A[p],           yi0 = g_A[p + BS];
    float yr1 = g_A[p + PL],      yi1 = g_A[p + PL + BS];
    float yr2 = g_A[p + 2 * PL],  yi2 = g_A[p + 2 * PL + BS];
    float yr3 = g_A[p + 3 * PL],  yi3 = g_A[p + 3 * PL + BS];

    // z[j] = sum_k Y[k] * e^{+2 pi i j k / 4}
    float zr0 = yr0 + yr1 + yr2 + yr3;
    float zi0 = yi0 + yi1 + yi2 + yi3;
    float zr1 = yr0 - yi1 - yr2 + yi3;
    float zi1 = yi0 + yr1 - yi2 - yr3;
    float zr2 = yr0 - yr1 + yr2 - yr3;
    float zi2 = yi0 - yi1 + yi2 - yi3;
    float zr3 = yr0 + yi1 - yr2 - yi3;
    float zi3 = yi0 - yr1 - yi2 + yr3;

    const size_t base = (size_t)m * C_DIM + d;
    g_Fr[base]          = zr0;  g_Fi[base]          = zi0;
    g_Fr[base + BS]     = zr1;  g_Fi[base + BS]     = zi1;
    g_Fr[base + 2 * BS] = zr2;  g_Fi[base + 2 * BS] = zi2;
    g_Fr[base + 3 * BS] = zr3;  g_Fi[base + 3 * BS] = zi3;
}

// ============================================================================
// K7: inverse FFT-4096 along seq (unnormalized) then * 1/128, real part out.
// ============================================================================
__global__ void fft_n_inv(float* __restrict__ out) {
    extern __shared__ float sm[];
    float* sr = sm;
    float* si = sm + 4 * N_DIM;

    const int b  = blockIdx.x / (C_DIM / 4);
    const int c0 = (blockIdx.x % (C_DIM / 4)) * 4;
    const int tid = threadIdx.x;

    for (int n = tid; n < N_DIM; n += blockDim.x) {
        size_t o = ((size_t)(b * N_DIM + n)) * C_DIM + c0;
        float4 vr = *(const float4*)&g_Fr[o];
        float4 vi = *(const float4*)&g_Fi[o];
        int r = __brev((unsigned)n) >> 20;
        sr[0 * N_DIM + r] = vr.x;  sr[1 * N_DIM + r] = vr.y;
        sr[2 * N_DIM + r] = vr.z;  sr[3 * N_DIM + r] = vr.w;
        si[0 * N_DIM + r] = vi.x;  si[1 * N_DIM + r] = vi.y;
        si[2 * N_DIM + r] = vi.z;  si[3 * N_DIM + r] = vi.w;
    }
    __syncthreads();

    for (int len = 2; len <= N_DIM; len <<= 1) {
        const int half = len >> 1;
        const float ang0 = 6.283185307179586f / (float)len;   // +: inverse
        for (int idx = tid; idx < 4 * (N_DIM / 2); idx += blockDim.x) {
            const int col = idx >> 11;
            const int j   = idx & (N_DIM / 2 - 1);
            const int pos = j & (half - 1);
            const int i0  = ((j - pos) << 1) + pos;
            const int i1  = i0 + half;
            float s, c;
            __sincosf(ang0 * (float)pos, &s, &c);
            float* pr = sr + col * N_DIM;
            float* pi = si + col * N_DIM;
            float xr = pr[i1], xi = pi[i1];
            float vr = xr * c - xi * s;
            float vi = xr * s + xi * c;
            float ur = pr[i0], ui = pi[i0];
            pr[i0] = ur + vr;  pi[i0] = ui + vi;
            pr[i1] = ur - vr;  pi[i1] = ui - vi;
        }
        __syncthreads();
    }

    for (int n = tid; n < N_DIM; n += blockDim.x) {
        float4 o = make_float4(sr[0 * N_DIM + n] * INV128,
                               sr[1 * N_DIM + n] * INV128,
                               sr[2 * N_DIM + n] * INV128,
                               sr[3 * N_DIM + n] * INV128);
        *(float4*)&out[((size_t)(b * N_DIM + n)) * C_DIM + c0] = o;
    }
}

// ============================================================================
// launch
// ============================================================================
extern "C" void kernel_launch(void* const* d_in, const int* in_sizes, int n_in,
                              void* d_out, int out_size) {
    (void)in_sizes; (void)n_in; (void)out_size;
    const float* x  = (const float*)d_in[0];
    const float* w1 = (const float*)d_in[1];
    const float* b1 = (const float*)d_in[2];
    const float* w2 = (const float*)d_in[3];
    const float* b2 = (const float*)d_in[4];
    float* out = (float*)d_out;

    const int FFT_SMEM = 4 * N_DIM * 2 * (int)sizeof(float);   // 131072
    cudaFuncSetAttribute(fft_n_fwd, cudaFuncAttributeMaxDynamicSharedMemorySize, FFT_SMEM);
    cudaFuncSetAttribute(fft_n_inv, cudaFuncAttributeMaxDynamicSharedMemorySize, FFT_SMEM);

    // K1: forward FFT along seq
    fft_n_fwd<<<B_DIM * (C_DIM / 4), 512, FFT_SMEM>>>(x);

    // K2: FFT-4 + ortho scale + pack
    fft4_pack<<<(M_TOT * BS) / 256, 256>>>();

    // K3: stacked weights
    prep_weights<<<(NB * KS * KS + 255) / 256, 256>>>(w1, b1, w2, b2);

    // K4/K5: MLP GEMMs
    dim3 gg(KS / 128, M_TOT / 128, NB);
    gemm_act<1><<<gg, 256>>>();
    gemm_act<2><<<gg, 256>>>();

    // K6: inverse FFT-4
    ifft4_unpack<<<(M_TOT * BS) / 256, 256>>>();

    // K7: inverse FFT along seq + real output
    fft_n_inv<<<B_DIM * (C_DIM / 4), 512, FFT_SMEM>>>(out);
}

// round 6
// speedup vs baseline: 1.3865x; 1.3823x over previous
#include <cuda_runtime.h>
#include <cuda_bf16.h>
#include <cstdint>

// ============================================================================
// EinFFT (sm_103, vanilla PTX target) — HMMA mma.sync bf16x3 GEMM + smem FFT
//   (tcgen05 unavailable: harness PTX target is compute_103 without the 'a')
// ============================================================================

#define B_DIM 8
#define N_DIM 4096
#define C_DIM 768
#define BS    192
#define NB    4
#define M_TOT (B_DIM * N_DIM)      // 32768
#define KS    384                  // stacked [re|im]
#define GK    768                  // stored K: [hi(384) | lo(384)]
#define KCH   18                   // K chunks of 64 (effective K = 1152)
#define LAMBDA 0.01f
#define INV128 (1.0f / 128.0f)

#define FFT_THREADS 1024
#define FFT_SMEM ((8 * N_DIM + 2 * N_DIM) * 4)   // 128KB data + 32KB twiddle
#define STAGE_BYTES 32768                        // A 16KB + B 16KB per stage
#define GEMM_SMEM (3 * STAGE_BYTES)              // 98304

// -------- scratch (static device globals; no runtime allocation) ------------
static __device__ float          g_Fr [(size_t)B_DIM * N_DIM * C_DIM];
static __device__ float          g_Fi [(size_t)B_DIM * N_DIM * C_DIM];
static __device__ unsigned short g_Xb [(size_t)NB * M_TOT * GK];   // bf16 [hi|lo]
static __device__ unsigned short g_Hb [(size_t)NB * M_TOT * GK];   // bf16 [hi|lo]
static __device__ unsigned short g_W1b[(size_t)NB * KS * GK];      // Wt bf16 [hi|lo]
static __device__ unsigned short g_W2b[(size_t)NB * KS * GK];
static __device__ float          g_B1 [NB * KS];
static __device__ float          g_B2 [NB * KS];
static __device__ float          g_P  [(size_t)NB * M_TOT * KS];   // fp32 MLP out

// ============================================================================
// helpers (all arch-neutral PTX: cp.async / ldmatrix / mma.sync)
// ============================================================================
__device__ __forceinline__ uint32_t smem_u32(const void* p) {
    uint32_t a;
    asm("{ .reg .u64 t; cvta.to.shared.u64 t, %1; cvt.u32.u64 %0, t; }"
        : "=r"(a) : "l"(p));
    return a;
}
__device__ __forceinline__ uint32_t swz128(uint32_t off) {
    return off ^ ((off >> 3) & 0x70);
}
__device__ __forceinline__ void cp16(uint32_t s, const void* g) {
    asm volatile("cp.async.cg.shared.global [%0], [%1], 16;" :: "r"(s), "l"(g));
}
__device__ __forceinline__ void ldsm_x4(uint32_t* r, uint32_t addr) {
    asm volatile("ldmatrix.sync.aligned.m8n8.x4.shared.b16 {%0,%1,%2,%3}, [%4];"
        : "=r"(r[0]), "=r"(r[1]), "=r"(r[2]), "=r"(r[3]) : "r"(addr));
}
__device__ __forceinline__ void mma16816(float* c, const uint32_t* a,
                                         uint32_t b0, uint32_t b1) {
    asm volatile(
        "mma.sync.aligned.m16n8k16.row.col.f32.bf16.bf16.f32 "
        "{%0,%1,%2,%3}, {%4,%5,%6,%7}, {%8,%9}, {%0,%1,%2,%3};"
        : "+f"(c[0]), "+f"(c[1]), "+f"(c[2]), "+f"(c[3])
        : "r"(a[0]), "r"(a[1]), "r"(a[2]), "r"(a[3]), "r"(b0), "r"(b1));
}

// chunk c -> (A k-offset, W k-offset) in bf16 elems within the GK=768 row.
// c in [0,6): hi*hi;  [6,12): a_hi*w_lo;  [12,18): a_lo*w_hi
__device__ __forceinline__ void chunk_offsets(int c, int& aoff, int& boff) {
    if (c < 6)       { aoff = c * 64;              boff = c * 64; }
    else if (c < 12) { aoff = (c - 6) * 64;        boff = 384 + (c - 6) * 64; }
    else             { aoff = 384 + (c - 12) * 64; boff = (c - 12) * 64; }
}

// load one K-chunk: A 128x64 bf16 (16KB) + B 128x64 bf16 (16KB), SW128 swizzle
__device__ __forceinline__ void load_chunk(const unsigned short* __restrict__ A,
                                           const unsigned short* __restrict__ W,
                                           uint32_t sA, uint32_t sB,
                                           int aoff, int boff, int tid) {
    #pragma unroll
    for (int t = 0; t < 4; t++) {
        int idx = tid + t * 256;          // 1024 x 16B
        int r = idx >> 3, i = idx & 7;
        cp16(sA + swz128((uint32_t)(r * 128 + i * 16)),
             A + (size_t)r * GK + aoff + i * 8);
    }
    #pragma unroll
    for (int t = 0; t < 4; t++) {
        int idx = tid + t * 256;
        int r = idx >> 3, i = idx & 7;
        cp16(sB + swz128((uint32_t)(r * 128 + i * 16)),
             W + (size_t)r * GK + boff + i * 8);
    }
    asm volatile("cp.async.commit_group;" ::: "memory");
}

// ============================================================================
// FFT-4096 along seq (radix-2 DIT, smem, stage-contiguous twiddle table)
// ============================================================================
template <int DIR>   // -1 forward, +1 inverse
static __device__ __forceinline__ void fft_core(float* sr, float* si, float2* tw, int tid) {
    for (int j = tid; j < N_DIM - 1; j += FFT_THREADS) {
        int half = 1 << (31 - __clz(j + 1));
        int pos  = (j + 1) - half;
        float s, c;
        __sincosf(-3.14159265358979f * (float)pos / (float)half, &s, &c);
        tw[j] = make_float2(c, s);
    }
    __syncthreads();
    for (int len = 2; len <= N_DIM; len <<= 1) {
        const int half = len >> 1;
        for (int idx = tid; idx < 4 * (N_DIM / 2); idx += FFT_THREADS) {
            const int col = idx >> 11;
            const int j   = idx & (N_DIM / 2 - 1);
            const int pos = j & (half - 1);
            const int i0  = ((j - pos) << 1) + pos;
            const int i1  = i0 + half;
            float2 t = tw[half - 1 + pos];
            float c = t.x;
            float s = (DIR < 0) ? t.y : -t.y;
            float* pr = sr + col * N_DIM;
            float* pi = si + col * N_DIM;
            float xr = pr[i1], xi = pi[i1];
            float vr = xr * c - xi * s;
            float vi = xr * s + xi * c;
            float ur = pr[i0], ui = pi[i0];
            pr[i0] = ur + vr;  pi[i0] = ui + vi;
            pr[i1] = ur - vr;  pi[i1] = ui - vi;
        }
        __syncthreads();
    }
}

__global__ __launch_bounds__(FFT_THREADS, 1) void fft_n_fwd(const float* __restrict__ x) {
    extern __shared__ float sm[];
    float* sr = sm;
    float* si = sm + 4 * N_DIM;
    float2* tw = (float2*)(sm + 8 * N_DIM);
    const int b  = blockIdx.x / (C_DIM / 4);
    const int c0 = (blockIdx.x % (C_DIM / 4)) * 4;
    const int tid = threadIdx.x;

    for (int n = tid; n < N_DIM; n += FFT_THREADS) {
        float4 v = *(const float4*)&x[((size_t)(b * N_DIM + n)) * C_DIM + c0];
        int r = __brev((unsigned)n) >> 20;
        sr[0 * N_DIM + r] = v.x;  sr[1 * N_DIM + r] = v.y;
        sr[2 * N_DIM + r] = v.z;  sr[3 * N_DIM + r] = v.w;
        si[0 * N_DIM + r] = 0.f;  si[1 * N_DIM + r] = 0.f;
        si[2 * N_DIM + r] = 0.f;  si[3 * N_DIM + r] = 0.f;
    }
    __syncthreads();
    fft_core<-1>(sr, si, tw, tid);
    for (int k = tid; k < N_DIM; k += FFT_THREADS) {
        size_t o = ((size_t)(b * N_DIM + k)) * C_DIM + c0;
        *(float4*)&g_Fr[o] = make_float4(sr[k], sr[N_DIM + k], sr[2 * N_DIM + k], sr[3 * N_DIM + k]);
        *(float4*)&g_Fi[o] = make_float4(si[k], si[N_DIM + k], si[2 * N_DIM + k], si[3 * N_DIM + k]);
    }
}

__global__ __launch_bounds__(FFT_THREADS, 1) void fft_n_inv(float* __restrict__ out) {
    extern __shared__ float sm[];
    float* sr = sm;
    float* si = sm + 4 * N_DIM;
    float2* tw = (float2*)(sm + 8 * N_DIM);
    const int b  = blockIdx.x / (C_DIM / 4);
    const int c0 = (blockIdx.x % (C_DIM / 4)) * 4;
    const int tid = threadIdx.x;

    for (int n = tid; n < N_DIM; n += FFT_THREADS) {
        size_t o = ((size_t)(b * N_DIM + n)) * C_DIM + c0;
        float4 vr = *(const float4*)&g_Fr[o];
        float4 vi = *(const float4*)&g_Fi[o];
        int r = __brev((unsigned)n) >> 20;
        sr[0 * N_DIM + r] = vr.x;  sr[1 * N_DIM + r] = vr.y;
        sr[2 * N_DIM + r] = vr.z;  sr[3 * N_DIM + r] = vr.w;
        si[0 * N_DIM + r] = vi.x;  si[1 * N_DIM + r] = vi.y;
        si[2 * N_DIM + r] = vi.z;  si[3 * N_DIM + r] = vi.w;
    }
    __syncthreads();
    fft_core<+1>(sr, si, tw, tid);
    for (int n = tid; n < N_DIM; n += FFT_THREADS) {
        float4 o = make_float4(sr[n] * INV128, sr[N_DIM + n] * INV128,
                               sr[2 * N_DIM + n] * INV128, sr[3 * N_DIM + n] * INV128);
        *(float4*)&out[((size_t)(b * N_DIM + n)) * C_DIM + c0] = o;
    }
}

// ============================================================================
// K2: FFT-4 along block axis + 1/128 scale, pack bf16 hi/lo GEMM rows.
// Row layout (GK): [hi_re(0..191) hi_im(192..383) | lo_re lo_im]
// ============================================================================
__global__ void fft4_pack() {
    int idx = blockIdx.x * blockDim.x + threadIdx.x;
    if (idx >= M_TOT * BS) return;
    const int m = idx / BS;
    const int d = idx % BS;

    const size_t base = (size_t)m * C_DIM + d;
    float xr0 = g_Fr[base],          xi0 = g_Fi[base];
    float xr1 = g_Fr[base + BS],     xi1 = g_Fi[base + BS];
    float xr2 = g_Fr[base + 2 * BS], xi2 = g_Fi[base + 2 * BS];
    float xr3 = g_Fr[base + 3 * BS], xi3 = g_Fi[base + 3 * BS];

    float yr[4], yi[4];
    yr[0] = (xr0 + xr1 + xr2 + xr3) * INV128;  yi[0] = (xi0 + xi1 + xi2 + xi3) * INV128;
    yr[1] = (xr0 + xi1 - xr2 - xi3) * INV128;  yi[1] = (xi0 - xr1 - xi2 + xr3) * INV128;
    yr[2] = (xr0 - xr1 + xr2 - xr3) * INV128;  yi[2] = (xi0 - xi1 + xi2 - xi3) * INV128;
    yr[3] = (xr0 - xi1 - xr2 + xi3) * INV128;  yi[3] = (xi0 + xr1 - xi2 - xr3) * INV128;

    const size_t PLX = (size_t)M_TOT * GK;
    #pragma unroll
    for (int p = 0; p < 4; p++) {
        unsigned short* row = g_Xb + p * PLX + (size_t)m * GK;
        __nv_bfloat16 hr = __float2bfloat16(yr[p]);
        __nv_bfloat16 hi = __float2bfloat16(yi[p]);
        row[d]            = __bfloat16_as_ushort(hr);
        row[BS + d]       = __bfloat16_as_ushort(hi);
        row[KS + d]       = __bfloat16_as_ushort(__float2bfloat16(yr[p] - __bfloat162float(hr)));
        row[KS + BS + d]  = __bfloat16_as_ushort(__float2bfloat16(yi[p] - __bfloat162float(hi)));
    }
}

// ============================================================================
// K3: stacked weights, transposed + bf16 hi/lo.
// g_Wb[(blk*KS + n)*GK + k]: k<384 -> hi(Ws[k][n]), k>=384 -> lo(Ws[k-384][n])
// Ws = [[Wr, Wi], [-Wi, Wr]]
// ============================================================================
__global__ void prep_weights(const float* __restrict__ w1, const float* __restrict__ b1,
                             const float* __restrict__ w2, const float* __restrict__ b2) {
    int idx = blockIdx.x * blockDim.x + threadIdx.x;
    if (idx < NB * KS * GK) {
        int k   = idx % GK;
        int n   = (idx / GK) % KS;
        int blk = idx / (GK * KS);
        int kk  = (k >= KS) ? k - KS : k;
        bool lohalf = (k >= KS);
        int dd = (kk < BS) ? kk : kk - BS;
        int cc = (n  < BS) ? n  : n  - BS;
        bool rlo = kk < BS, clo = n < BS;
        size_t ir = ((size_t)blk        * BS + dd) * BS + cc;
        size_t ii = ((size_t)(NB + blk) * BS + dd) * BS + cc;
        float v1, v2;
        if (rlo == clo) { v1 =  w1[ir]; v2 =  w2[ir]; }
        else if (rlo)   { v1 =  w1[ii]; v2 =  w2[ii]; }
        else            { v1 = -w1[ii]; v2 = -w2[ii]; }
        __nv_bfloat16 h1 = __float2bfloat16(v1);
        __nv_bfloat16 h2 = __float2bfloat16(v2);
        if (lohalf) {
            g_W1b[idx] = __bfloat16_as_ushort(__float2bfloat16(v1 - __bfloat162float(h1)));
            g_W2b[idx] = __bfloat16_as_ushort(__float2bfloat16(v2 - __bfloat162float(h2)));
        } else {
            g_W1b[idx] = __bfloat16_as_ushort(h1);
            g_W2b[idx] = __bfloat16_as_ushort(h2);
        }
    }
    if (idx < NB * KS) {
        int blk = idx / KS;
        int c   = idx % KS;
        size_t ib = (c < BS) ? ((size_t)blk * BS + c)
                             : ((size_t)(NB + blk) * BS + (c - BS));
        g_B1[idx] = b1[ib];
        g_B2[idx] = b2[ib];
    }
}

// ============================================================================
// K4/K5: HMMA bf16x3 GEMM. CTA 128x128, 8 warps (4x2), warp tile 32x64.
// grid (3 n-tiles, 256 m-tiles, NB) — N fastest for A-tile L2 reuse.
//   LAYER 1: H(bf16 hi/lo) = relu(A @ W1 + b1)
//   LAYER 2: P(fp32)       = softshrink(H @ W2 + b2)
// ============================================================================
template <int LAYER>
__global__ __launch_bounds__(256, 1) void gemm_mma() {
    extern __shared__ __align__(1024) char smem_raw[];
    const uint32_t smem = smem_u32(smem_raw);
    const int tid    = threadIdx.x;
    const int wid    = tid >> 5;
    const int lane   = tid & 31;
    const int warp_m = wid & 3;          // 0..3 (rows of 32)
    const int warp_n = wid >> 2;         // 0..1 (cols of 64)
    const int n0     = blockIdx.x * 128;
    const int tile_m = blockIdx.y * 128;
    const int blk    = blockIdx.z;

    const unsigned short* A = (LAYER == 1 ? g_Xb : g_Hb)
                            + (size_t)blk * M_TOT * GK + (size_t)tile_m * GK;
    const unsigned short* W = (LAYER == 1 ? g_W1b : g_W2b)
                            + (size_t)blk * KS * GK + (size_t)n0 * GK;
    const float* bias       = (LAYER == 1 ? g_B1 : g_B2) + blk * KS;

    float acc[2][8][4];
    #pragma unroll
    for (int i = 0; i < 2; i++)
        #pragma unroll
        for (int j = 0; j < 8; j++)
            #pragma unroll
            for (int q = 0; q < 4; q++) acc[i][j][q] = 0.f;

    // prologue: stages 0..2
    #pragma unroll
    for (int c = 0; c < 3; c++) {
        int ao, bo; chunk_offsets(c, ao, bo);
        uint32_t sA = smem + c * STAGE_BYTES;
        load_chunk(A, W, sA, sA + 16384, ao, bo, tid);
    }

    // precomputed ldmatrix lane offsets (within a stage, pre-swizzle base parts)
    const uint32_t a_row = (uint32_t)(warp_m * 32 + (lane & 15));
    const uint32_t a_cb  = (uint32_t)((lane >> 4) * 16);
    const uint32_t b_row = (uint32_t)(warp_n * 64 + (lane & 7) + ((lane >> 4) * 8));
    const uint32_t b_cb  = (uint32_t)(((lane >> 3) & 1) * 16);

    for (int c = 0; c < KCH; c++) {
        if (c < KCH - 2)       asm volatile("cp.async.wait_group 2;" ::: "memory");
        else if (c == KCH - 2) asm volatile("cp.async.wait_group 1;" ::: "memory");
        else                   asm volatile("cp.async.wait_group 0;" ::: "memory");
        __syncthreads();

        const uint32_t sA = smem + (c % 3) * STAGE_BYTES;
        const uint32_t sB = sA + 16384;

        #pragma unroll
        for (int k16 = 0; k16 < 4; k16++) {
            uint32_t a[2][4];
            #pragma unroll
            for (int mi = 0; mi < 2; mi++)
                ldsm_x4(a[mi], sA + swz128((a_row + mi * 16) * 128 + k16 * 32 + a_cb));
            uint32_t b[4][4];
            #pragma unroll
            for (int nj = 0; nj < 4; nj++)
                ldsm_x4(b[nj], sB + swz128((b_row + nj * 16) * 128 + k16 * 32 + b_cb));
            #pragma unroll
            for (int mi = 0; mi < 2; mi++)
                #pragma unroll
                for (int nj = 0; nj < 4; nj++) {
                    mma16816(acc[mi][2 * nj],     a[mi], b[nj][0], b[nj][1]);
                    mma16816(acc[mi][2 * nj + 1], a[mi], b[nj][2], b[nj][3]);
                }
        }
        __syncthreads();
        if (c + 3 < KCH) {
            int ao, bo; chunk_offsets(c + 3, ao, bo);
            load_chunk(A, W, sA, sB, ao, bo, tid);
        }
    }

    // epilogue
    #pragma unroll
    for (int mi = 0; mi < 2; mi++) {
        #pragma unroll
        for (int na = 0; na < 8; na++) {
            const int col  = n0 + warp_n * 64 + na * 8 + 2 * (lane & 3);
            const int row0 = tile_m + warp_m * 32 + mi * 16 + (lane >> 2);
            const float b0 = bias[col], b1 = bias[col + 1];
            #pragma unroll
            for (int h = 0; h < 2; h++) {            // h=0: row0, h=1: row0+8
                const int row = row0 + h * 8;
                float v0 = acc[mi][na][2 * h]     + b0;
                float v1 = acc[mi][na][2 * h + 1] + b1;
                if (LAYER == 1) {
                    v0 = fmaxf(v0, 0.f);
                    v1 = fmaxf(v1, 0.f);
                    __nv_bfloat16 h0 = __float2bfloat16(v0);
                    __nv_bfloat16 h1 = __float2bfloat16(v1);
                    ushort2 hs = make_ushort2(__bfloat16_as_ushort(h0),
                                              __bfloat16_as_ushort(h1));
                    ushort2 ls = make_ushort2(
                        __bfloat16_as_ushort(__float2bfloat16(v0 - __bfloat162float(h0))),
                        __bfloat16_as_ushort(__float2bfloat16(v1 - __bfloat162float(h1))));
                    unsigned short* rb = g_Hb + ((size_t)blk * M_TOT + row) * GK;
                    *(ushort2*)(rb + col)      = hs;
                    *(ushort2*)(rb + KS + col) = ls;
                } else {
                    v0 = (v0 > LAMBDA) ? v0 - LAMBDA
                                       : ((v0 < -LAMBDA) ? v0 + LAMBDA : 0.f);
                    v1 = (v1 > LAMBDA) ? v1 - LAMBDA
                                       : ((v1 < -LAMBDA) ? v1 + LAMBDA : 0.f);
                    *(float2*)(g_P + ((size_t)blk * M_TOT + row) * KS + col)
                        = make_float2(v0, v1);
                }
            }
        }
    }
}

// ============================================================================
// K6: inverse FFT-4 along block axis (unnormalized), back to spectrum layout.
// ============================================================================
__global__ void ifft4_unpack() {
    int idx = blockIdx.x * blockDim.x + threadIdx.x;
    if (idx >= M_TOT * BS) return;
    const int m = idx / BS;
    const int d = idx % BS;

    const size_t PL = (size_t)M_TOT * KS;
    const size_t p  = (size_t)m * KS + d;
    float yr0 = g_P[p],           yi0 = g_P[p + BS];
    float yr1 = g_P[p + PL],      yi1 = g_P[p + PL + BS];
    float yr2 = g_P[p + 2 * PL],  yi2 = g_P[p + 2 * PL + BS];
    float yr3 = g_P[p + 3 * PL],  yi3 = g_P[p + 3 * PL + BS];

    float zr0 = yr0 + yr1 + yr2 + yr3;
    float zi0 = yi0 + yi1 + yi2 + yi3;
    float zr1 = yr0 - yi1 - yr2 + yi3;
    float zi1 = yi0 + yr1 - yi2 - yr3;
    float zr2 = yr0 - yr1 + yr2 - yr3;
    float zi2 = yi0 - yi1 + yi2 - yi3;
    float zr3 = yr0 + yi1 - yr2 - yi3;
    float zi3 = yi0 - yr1 - yi2 + yr3;

    const size_t base = (size_t)m * C_DIM + d;
    g_Fr[base]          = zr0;  g_Fi[base]          = zi0;
    g_Fr[base + BS]     = zr1;  g_Fi[base + BS]     = zi1;
    g_Fr[base + 2 * BS] = zr2;  g_Fi[base + 2 * BS] = zi2;
    g_Fr[base + 3 * BS] = zr3;  g_Fi[base + 3 * BS] = zi3;
}

// ============================================================================
// launch
// ============================================================================
extern "C" void kernel_launch(void* const* d_in, const int* in_sizes, int n_in,
                              void* d_out, int out_size) {
    (void)in_sizes; (void)n_in; (void)out_size;
    const float* x  = (const float*)d_in[0];
    const float* w1 = (const float*)d_in[1];
    const float* b1 = (const float*)d_in[2];
    const float* w2 = (const float*)d_in[3];
    const float* b2 = (const float*)d_in[4];
    float* out = (float*)d_out;

    cudaFuncSetAttribute(fft_n_fwd, cudaFuncAttributeMaxDynamicSharedMemorySize, FFT_SMEM);
    cudaFuncSetAttribute(fft_n_inv, cudaFuncAttributeMaxDynamicSharedMemorySize, FFT_SMEM);
    cudaFuncSetAttribute(gemm_mma<1>, cudaFuncAttributeMaxDynamicSharedMemorySize, GEMM_SMEM);
    cudaFuncSetAttribute(gemm_mma<2>, cudaFuncAttributeMaxDynamicSharedMemorySize, GEMM_SMEM);

    fft_n_fwd<<<B_DIM * (C_DIM / 4), FFT_THREADS, FFT_SMEM>>>(x);
    fft4_pack<<<(M_TOT * BS) / 256, 256>>>();
    prep_weights<<<(NB * KS * GK + 255) / 256, 256>>>(w1, b1, w2, b2);

    dim3 gg(3, M_TOT / 128, NB);
    gemm_mma<1><<<gg, 256, GEMM_SMEM>>>();
    gemm_mma<2><<<gg, 256, GEMM_SMEM>>>();

    ifft4_unpack<<<(M_TOT * BS) / 256, 256>>>();
    fft_n_inv<<<B_DIM * (C_DIM / 4), FFT_THREADS, FFT_SMEM>>>(out);
}

// round 7
// speedup vs baseline: 1.7386x; 1.2539x over previous
#include <cuda_runtime.h>
#include <cuda_bf16.h>
#include <cstdint>

// ============================================================================
// EinFFT (sm_103) — HMMA bf16x3 GEMM (4-stage single-sync pipeline)
//   + paired-real forward FFT + hermitian-packed inverse FFT
// ============================================================================

#define B_DIM 8
#define N_DIM 4096
#define C_DIM 768
#define BS    192
#define NB    4
#define M_TOT (B_DIM * N_DIM)      // 32768
#define KS    384                  // stacked [re|im]
#define GK    768                  // stored K: [hi(384) | lo(384)]
#define KCH   18                   // K chunks of 64 (effective K = 1152)
#define LAMBDA 0.01f
#define INV128 (1.0f / 128.0f)

#define FFT_THREADS 1024
#define FFT_SMEM ((8 * N_DIM + 2 * N_DIM) * 4)   // 128KB data + 32KB twiddle
#define STAGE_BYTES 32768                        // A 16KB + B 16KB per stage
#define NSTG 4
#define GEMM_SMEM (NSTG * STAGE_BYTES)           // 131072

// -------- scratch (static device globals; no runtime allocation) ------------
static __device__ float          g_Fr [(size_t)B_DIM * N_DIM * C_DIM];
static __device__ float          g_Fi [(size_t)B_DIM * N_DIM * C_DIM];
static __device__ unsigned short g_Xb [(size_t)NB * M_TOT * GK];   // bf16 [hi|lo]
static __device__ unsigned short g_Hb [(size_t)NB * M_TOT * GK];   // bf16 [hi|lo]
static __device__ unsigned short g_W1b[(size_t)NB * KS * GK];      // Wt bf16 [hi|lo]
static __device__ unsigned short g_W2b[(size_t)NB * KS * GK];
static __device__ float          g_B1 [NB * KS];
static __device__ float          g_B2 [NB * KS];
static __device__ float          g_P  [(size_t)NB * M_TOT * KS];   // fp32 MLP out
static __device__ float2         g_Wc [(size_t)NB * M_TOT * 96];   // packed herm spectrum

// ============================================================================
// helpers (arch-neutral PTX only)
// ============================================================================
__device__ __forceinline__ uint32_t smem_u32(const void* p) {
    uint32_t a;
    asm("{ .reg .u64 t; cvta.to.shared.u64 t, %1; cvt.u32.u64 %0, t; }"
        : "=r"(a) : "l"(p));
    return a;
}
__device__ __forceinline__ uint32_t swz128(uint32_t off) {
    return off ^ ((off >> 3) & 0x70);
}
__device__ __forceinline__ void cp16(uint32_t s, const void* g) {
    asm volatile("cp.async.cg.shared.global [%0], [%1], 16;" :: "r"(s), "l"(g));
}
__device__ __forceinline__ void ldsm_x4(uint32_t* r, uint32_t addr) {
    asm volatile("ldmatrix.sync.aligned.m8n8.x4.shared.b16 {%0,%1,%2,%3}, [%4];"
        : "=r"(r[0]), "=r"(r[1]), "=r"(r[2]), "=r"(r[3]) : "r"(addr));
}
__device__ __forceinline__ void mma16816(float* c, const uint32_t* a,
                                         uint32_t b0, uint32_t b1) {
    asm volatile(
        "mma.sync.aligned.m16n8k16.row.col.f32.bf16.bf16.f32 "
        "{%0,%1,%2,%3}, {%4,%5,%6,%7}, {%8,%9}, {%0,%1,%2,%3};"
        : "+f"(c[0]), "+f"(c[1]), "+f"(c[2]), "+f"(c[3])
        : "r"(a[0]), "r"(a[1]), "r"(a[2]), "r"(a[3]), "r"(b0), "r"(b1));
}

// chunk c -> (A k-offset, W k-offset). [0,6): hi*hi; [6,12): a_hi*w_lo; [12,18): a_lo*w_hi
__device__ __forceinline__ void chunk_offsets(int c, int& aoff, int& boff) {
    if (c < 6)       { aoff = c * 64;              boff = c * 64; }
    else if (c < 12) { aoff = (c - 6) * 64;        boff = 384 + (c - 6) * 64; }
    else             { aoff = 384 + (c - 12) * 64; boff = (c - 12) * 64; }
}

__device__ __forceinline__ void load_chunk(const unsigned short* __restrict__ A,
                                           const unsigned short* __restrict__ W,
                                           uint32_t sA, uint32_t sB,
                                           int aoff, int boff, int tid) {
    #pragma unroll
    for (int t = 0; t < 4; t++) {
        int idx = tid + t * 256;
        int r = idx >> 3, i = idx & 7;
        cp16(sA + swz128((uint32_t)(r * 128 + i * 16)),
             A + (size_t)r * GK + aoff + i * 8);
    }
    #pragma unroll
    for (int t = 0; t < 4; t++) {
        int idx = tid + t * 256;
        int r = idx >> 3, i = idx & 7;
        cp16(sB + swz128((uint32_t)(r * 128 + i * 16)),
             W + (size_t)r * GK + boff + i * 8);
    }
    asm volatile("cp.async.commit_group;" ::: "memory");
}

// ============================================================================
// FFT-4096 core (radix-2 DIT, smem, stage-contiguous twiddle table; 4 columns)
// ============================================================================
template <int DIR>   // -1 forward, +1 inverse
static __device__ __forceinline__ void fft_core(float* sr, float* si, float2* tw, int tid) {
    for (int j = tid; j < N_DIM - 1; j += FFT_THREADS) {
        int half = 1 << (31 - __clz(j + 1));
        int pos  = (j + 1) - half;
        float s, c;
        __sincosf(-3.14159265358979f * (float)pos / (float)half, &s, &c);
        tw[j] = make_float2(c, s);
    }
    __syncthreads();
    for (int len = 2; len <= N_DIM; len <<= 1) {
        const int half = len >> 1;
        for (int idx = tid; idx < 4 * (N_DIM / 2); idx += FFT_THREADS) {
            const int col = idx >> 11;
            const int j   = idx & (N_DIM / 2 - 1);
            const int pos = j & (half - 1);
            const int i0  = ((j - pos) << 1) + pos;
            const int i1  = i0 + half;
            float2 t = tw[half - 1 + pos];
            float c = t.x;
            float s = (DIR < 0) ? t.y : -t.y;
            float* pr = sr + col * N_DIM;
            float* pi = si + col * N_DIM;
            float xr = pr[i1], xi = pi[i1];
            float vr = xr * c - xi * s;
            float vi = xr * s + xi * c;
            float ur = pr[i0], ui = pi[i0];
            pr[i0] = ur + vr;  pi[i0] = ui + vi;
            pr[i1] = ur - vr;  pi[i1] = ui - vi;
        }
        __syncthreads();
    }
}

// ============================================================================
// K1: forward FFT-4096, paired-real. One CTA = 8 channels as 4 complex cols
//   (x[c]+i*x[c+1]); unpack via F_a=(P[k]+conj(P[-k]))/2, F_b=(P[k]-conj(P[-k]))/2i
// ============================================================================
__global__ __launch_bounds__(FFT_THREADS, 1) void fft_n_fwd(const float* __restrict__ x) {
    extern __shared__ float sm[];
    float* sr = sm;
    float* si = sm + 4 * N_DIM;
    float2* tw = (float2*)(sm + 8 * N_DIM);
    const int b  = blockIdx.x / 96;
    const int c0 = (blockIdx.x % 96) * 8;
    const int tid = threadIdx.x;

    for (int n = tid; n < N_DIM; n += FFT_THREADS) {
        const float* row = &x[((size_t)(b * N_DIM + n)) * C_DIM + c0];
        float4 v0 = *(const float4*)row;
        float4 v1 = *(const float4*)(row + 4);
        int r = __brev((unsigned)n) >> 20;
        sr[0 * N_DIM + r] = v0.x;  si[0 * N_DIM + r] = v0.y;
        sr[1 * N_DIM + r] = v0.z;  si[1 * N_DIM + r] = v0.w;
        sr[2 * N_DIM + r] = v1.x;  si[2 * N_DIM + r] = v1.y;
        sr[3 * N_DIM + r] = v1.z;  si[3 * N_DIM + r] = v1.w;
    }
    __syncthreads();
    fft_core<-1>(sr, si, tw, tid);

    for (int k = tid; k < N_DIM; k += FFT_THREADS) {
        const int kr = (N_DIM - k) & (N_DIM - 1);
        float fr[8], fi[8];
        #pragma unroll
        for (int t = 0; t < 4; t++) {
            float pr = sr[t * N_DIM + k],  pi_ = si[t * N_DIM + k];
            float qr = sr[t * N_DIM + kr], qi  = si[t * N_DIM + kr];
            fr[2 * t]     = 0.5f * (pr + qr);
            fi[2 * t]     = 0.5f * (pi_ - qi);
            fr[2 * t + 1] = 0.5f * (pi_ + qi);
            fi[2 * t + 1] = 0.5f * (qr - pr);
        }
        size_t o = ((size_t)(b * N_DIM + k)) * C_DIM + c0;
        *(float4*)&g_Fr[o]     = *(float4*)&fr[0];
        *(float4*)&g_Fr[o + 4] = *(float4*)&fr[4];
        *(float4*)&g_Fi[o]     = *(float4*)&fi[0];
        *(float4*)&g_Fi[o + 4] = *(float4*)&fi[4];
    }
}

// ============================================================================
// K2: FFT-4 along block axis + 1/128 scale, pack bf16 hi/lo GEMM rows.
// ============================================================================
__global__ void fft4_pack() {
    int idx = blockIdx.x * blockDim.x + threadIdx.x;
    if (idx >= M_TOT * BS) return;
    const int m = idx / BS;
    const int d = idx % BS;

    const size_t base = (size_t)m * C_DIM + d;
    float xr0 = g_Fr[base],          xi0 = g_Fi[base];
    float xr1 = g_Fr[base + BS],     xi1 = g_Fi[base + BS];
    float xr2 = g_Fr[base + 2 * BS], xi2 = g_Fi[base + 2 * BS];
    float xr3 = g_Fr[base + 3 * BS], xi3 = g_Fi[base + 3 * BS];

    float yr[4], yi[4];
    yr[0] = (xr0 + xr1 + xr2 + xr3) * INV128;  yi[0] = (xi0 + xi1 + xi2 + xi3) * INV128;
    yr[1] = (xr0 + xi1 - xr2 - xi3) * INV128;  yi[1] = (xi0 - xr1 - xi2 + xr3) * INV128;
    yr[2] = (xr0 - xr1 + xr2 - xr3) * INV128;  yi[2] = (xi0 - xi1 + xi2 - xi3) * INV128;
    yr[3] = (xr0 - xi1 - xr2 + xi3) * INV128;  yi[3] = (xi0 + xr1 - xi2 - xr3) * INV128;

    const size_t PLX = (size_t)M_TOT * GK;
    #pragma unroll
    for (int p = 0; p < 4; p++) {
        unsigned short* row = g_Xb + p * PLX + (size_t)m * GK;
        __nv_bfloat16 hr = __float2bfloat16(yr[p]);
        __nv_bfloat16 hi = __float2bfloat16(yi[p]);
        row[d]            = __bfloat16_as_ushort(hr);
        row[BS + d]       = __bfloat16_as_ushort(hi);
        row[KS + d]       = __bfloat16_as_ushort(__float2bfloat16(yr[p] - __bfloat162float(hr)));
        row[KS + BS + d]  = __bfloat16_as_ushort(__float2bfloat16(yi[p] - __bfloat162float(hi)));
    }
}

// ============================================================================
// K3: stacked weights, transposed + bf16 hi/lo.  Ws = [[Wr, Wi], [-Wi, Wr]]
// ============================================================================
__global__ void prep_weights(const float* __restrict__ w1, const float* __restrict__ b1,
                             const float* __restrict__ w2, const float* __restrict__ b2) {
    int idx = blockIdx.x * blockDim.x + threadIdx.x;
    if (idx < NB * KS * GK) {
        int k   = idx % GK;
        int n   = (idx / GK) % KS;
        int blk = idx / (GK * KS);
        int kk  = (k >= KS) ? k - KS : k;
        bool lohalf = (k >= KS);
        int dd = (kk < BS) ? kk : kk - BS;
        int cc = (n  < BS) ? n  : n  - BS;
        bool rlo = kk < BS, clo = n < BS;
        size_t ir = ((size_t)blk        * BS + dd) * BS + cc;
        size_t ii = ((size_t)(NB + blk) * BS + dd) * BS + cc;
        float v1, v2;
        if (rlo == clo) { v1 =  w1[ir]; v2 =  w2[ir]; }
        else if (rlo)   { v1 =  w1[ii]; v2 =  w2[ii]; }
        else            { v1 = -w1[ii]; v2 = -w2[ii]; }
        __nv_bfloat16 h1 = __float2bfloat16(v1);
        __nv_bfloat16 h2 = __float2bfloat16(v2);
        if (lohalf) {
            g_W1b[idx] = __bfloat16_as_ushort(__float2bfloat16(v1 - __bfloat162float(h1)));
            g_W2b[idx] = __bfloat16_as_ushort(__float2bfloat16(v2 - __bfloat162float(h2)));
        } else {
            g_W1b[idx] = __bfloat16_as_ushort(h1);
            g_W2b[idx] = __bfloat16_as_ushort(h2);
        }
    }
    if (idx < NB * KS) {
        int blk = idx / KS;
        int c   = idx % KS;
        size_t ib = (c < BS) ? ((size_t)blk * BS + c)
                             : ((size_t)(NB + blk) * BS + (c - BS));
        g_B1[idx] = b1[ib];
        g_B2[idx] = b2[ib];
    }
}

// ============================================================================
// K4/K5: HMMA bf16x3 GEMM. CTA 128x128, 8 warps (4x2), warp tile 32x64.
// 4-stage cp.async pipeline, ONE __syncthreads per chunk, frag double-buffer.
// ============================================================================
template <int LAYER>
__global__ __launch_bounds__(256, 1) void gemm_mma() {
    extern __shared__ __align__(1024) char smem_raw[];
    const uint32_t smem = smem_u32(smem_raw);
    const int tid    = threadIdx.x;
    const int wid    = tid >> 5;
    const int lane   = tid & 31;
    const int warp_m = wid & 3;
    const int warp_n = wid >> 2;
    const int n0     = blockIdx.x * 128;
    const int tile_m = blockIdx.y * 128;
    const int blk    = blockIdx.z;

    const unsigned short* A = (LAYER == 1 ? g_Xb : g_Hb)
                            + (size_t)blk * M_TOT * GK + (size_t)tile_m * GK;
    const unsigned short* W = (LAYER == 1 ? g_W1b : g_W2b)
                            + (size_t)blk * KS * GK + (size_t)n0 * GK;
    const float* bias       = (LAYER == 1 ? g_B1 : g_B2) + blk * KS;

    float acc[2][8][4];
    #pragma unroll
    for (int i = 0; i < 2; i++)
        #pragma unroll
        for (int j = 0; j < 8; j++)
            #pragma unroll
            for (int q = 0; q < 4; q++) acc[i][j][q] = 0.f;

    // prologue: stages 0..2
    #pragma unroll
    for (int c = 0; c < 3; c++) {
        int ao, bo; chunk_offsets(c, ao, bo);
        uint32_t sA = smem + c * STAGE_BYTES;
        load_chunk(A, W, sA, sA + 16384, ao, bo, tid);
    }

    const uint32_t a_row = (uint32_t)(warp_m * 32 + (lane & 15));
    const uint32_t a_cb  = (uint32_t)((lane >> 4) * 16);
    const uint32_t b_row = (uint32_t)(warp_n * 64 + (lane & 7) + ((lane >> 4) * 8));
    const uint32_t b_cb  = (uint32_t)(((lane >> 3) & 1) * 16);

    uint32_t af[2][2][4], bf[2][4][4];

    for (int c = 0; c < KCH; c++) {
        if (c < KCH - 2)       asm volatile("cp.async.wait_group 2;" ::: "memory");
        else if (c == KCH - 2) asm volatile("cp.async.wait_group 1;" ::: "memory");
        else                   asm volatile("cp.async.wait_group 0;" ::: "memory");
        __syncthreads();   // all warps done reading stage (c-1)%NSTG

        // overlap: load chunk c+3 into the stage freed last iteration
        if (c + 3 < KCH) {
            int ao, bo; chunk_offsets(c + 3, ao, bo);
            uint32_t sL = smem + ((c + 3) % NSTG) * STAGE_BYTES;
            load_chunk(A, W, sL, sL + 16384, ao, bo, tid);
        }

        const uint32_t sA = smem + (c % NSTG) * STAGE_BYTES;
        const uint32_t sB = sA + 16384;

        // fragment double-buffered k16 loop
        #pragma unroll
        for (int mi = 0; mi < 2; mi++)
            ldsm_x4(af[0][mi], sA + swz128((a_row + mi * 16) * 128 + a_cb));
        #pragma unroll
        for (int nj = 0; nj < 4; nj++)
            ldsm_x4(bf[0][nj], sB + swz128((b_row + nj * 16) * 128 + b_cb));

        #pragma unroll
        for (int k16 = 0; k16 < 4; k16++) {
            const int cur = k16 & 1, nxt = cur ^ 1;
            if (k16 < 3) {
                #pragma unroll
                for (int mi = 0; mi < 2; mi++)
                    ldsm_x4(af[nxt][mi],
                            sA + swz128((a_row + mi * 16) * 128 + (k16 + 1) * 32 + a_cb));
                #pragma unroll
                for (int nj = 0; nj < 4; nj++)
                    ldsm_x4(bf[nxt][nj],
                            sB + swz128((b_row + nj * 16) * 128 + (k16 + 1) * 32 + b_cb));
            }
            #pragma unroll
            for (int mi = 0; mi < 2; mi++)
                #pragma unroll
                for (int nj = 0; nj < 4; nj++) {
                    mma16816(acc[mi][2 * nj],     af[cur][mi], bf[cur][nj][0], bf[cur][nj][1]);
                    mma16816(acc[mi][2 * nj + 1], af[cur][mi], bf[cur][nj][2], bf[cur][nj][3]);
                }
        }
    }

    // epilogue
    #pragma unroll
    for (int mi = 0; mi < 2; mi++) {
        #pragma unroll
        for (int na = 0; na < 8; na++) {
            const int col  = n0 + warp_n * 64 + na * 8 + 2 * (lane & 3);
            const int row0 = tile_m + warp_m * 32 + mi * 16 + (lane >> 2);
            const float b0 = bias[col], b1 = bias[col + 1];
            #pragma unroll
            for (int h = 0; h < 2; h++) {
                const int row = row0 + h * 8;
                float v0 = acc[mi][na][2 * h]     + b0;
                float v1 = acc[mi][na][2 * h + 1] + b1;
                if (LAYER == 1) {
                    v0 = fmaxf(v0, 0.f);
                    v1 = fmaxf(v1, 0.f);
                    __nv_bfloat16 h0 = __float2bfloat16(v0);
                    __nv_bfloat16 h1 = __float2bfloat16(v1);
                    ushort2 hs = make_ushort2(__bfloat16_as_ushort(h0),
                                              __bfloat16_as_ushort(h1));
                    ushort2 ls = make_ushort2(
                        __bfloat16_as_ushort(__float2bfloat16(v0 - __bfloat162float(h0))),
                        __bfloat16_as_ushort(__float2bfloat16(v1 - __bfloat162float(h1))));
                    unsigned short* rb = g_Hb + ((size_t)blk * M_TOT + row) * GK;
                    *(ushort2*)(rb + col)      = hs;
                    *(ushort2*)(rb + KS + col) = ls;
                } else {
                    v0 = (v0 > LAMBDA) ? v0 - LAMBDA
                                       : ((v0 < -LAMBDA) ? v0 + LAMBDA : 0.f);
                    v1 = (v1 > LAMBDA) ? v1 - LAMBDA
                                       : ((v1 < -LAMBDA) ? v1 + LAMBDA : 0.f);
                    *(float2*)(g_P + ((size_t)blk * M_TOT + row) * KS + col)
                        = make_float2(v0, v1);
                }
            }
        }
    }
}

// ============================================================================
// K6: inverse FFT-4 along block axis + hermitian channel-pair packing.
// For channel pair (2dp, 2dp+1) of block j, rows k and N-k:
//   V1[k] = (z_j(k,2dp)   + conj(z_j(N-k,2dp)))/2
//   V2[k] = (z_j(k,2dp+1) + conj(z_j(N-k,2dp+1)))/2
//   W_j[k] = V1[k] + i*V2[k]   ->  ifft(W) = out(2dp) + i*out(2dp+1), both real
// ============================================================================
__global__ void ifft4_wpack() {
    const int idx = blockIdx.x * blockDim.x + threadIdx.x;
    const int total = B_DIM * 2049 * 96;
    if (idx >= total) return;
    const int dp   = idx % 96;
    const int kpos = (idx / 96) % 2049;
    const int b    = idx / (96 * 2049);
    const int d    = 2 * dp;
    const int m1   = b * N_DIM + kpos;
    const int m2   = b * N_DIM + ((N_DIM - kpos) & (N_DIM - 1));

    const size_t PL = (size_t)M_TOT * KS;

    float z1r[4], z1i[4], z2r[4], z2i[4];   // z_j at (m,d), (m,d+1) — per row
    #pragma unroll
    for (int rowsel = 0; rowsel < 2; rowsel++) {
        const int m = rowsel ? m2 : m1;
        float yrA[4], yiA[4], yrB[4], yiB[4];     // Y_k2 at d, d+1
        #pragma unroll
        for (int k2 = 0; k2 < 4; k2++) {
            const float* pp = g_P + k2 * PL + (size_t)m * KS;
            float2 re = *(const float2*)(pp + d);
            float2 im = *(const float2*)(pp + BS + d);
            yrA[k2] = re.x;  yrB[k2] = re.y;
            yiA[k2] = im.x;  yiB[k2] = im.y;
        }
        // z_j = sum_k2 Y_k2 e^{+2pi i j k2/4}
        float zrA[4], ziA[4], zrB[4], ziB[4];
        zrA[0] = yrA[0] + yrA[1] + yrA[2] + yrA[3];
        ziA[0] = yiA[0] + yiA[1] + yiA[2] + yiA[3];
        zrA[1] = yrA[0] - yiA[1] - yrA[2] + yiA[3];
        ziA[1] = yiA[0] + yrA[1] - yiA[2] - yrA[3];
        zrA[2] = yrA[0] - yrA[1] + yrA[2] - yrA[3];
        ziA[2] = yiA[0] - yiA[1] + yiA[2] - yiA[3];
        zrA[3] = yrA[0] + yiA[1] - yrA[2] - yiA[3];
        ziA[3] = yiA[0] - yrA[1] - yiA[2] + yrA[3];
        zrB[0] = yrB[0] + yrB[1] + yrB[2] + yrB[3];
        ziB[0] = yiB[0] + yiB[1] + yiB[2] + yiB[3];
        zrB[1] = yrB[0] - yiB[1] - yrB[2] + yiB[3];
        ziB[1] = yiB[0] + yrB[1] - yiB[2] - yrB[3];
        zrB[2] = yrB[0] - yrB[1] + yrB[2] - yrB[3];
        ziB[2] = yiB[0] - yiB[1] + yiB[2] - yiB[3];
        zrB[3] = yrB[0] + yiB[1] - yrB[2] - yiB[3];
        ziB[3] = yiB[0] - yrB[1] - yiB[2] + yrB[3];
        if (rowsel == 0) {
            #pragma unroll
            for (int j = 0; j < 4; j++) {
                z1r[j] = zrA[j]; z1i[j] = ziA[j];
                z2r[j] = zrB[j]; z2i[j] = ziB[j];
            }
        } else {
            // write both W[k] and W[N-k] for all 4 blocks
            #pragma unroll
            for (int j = 0; j < 4; j++) {
                float v1r = 0.5f * (z1r[j] + zrA[j]);
                float v1i = 0.5f * (z1i[j] - ziA[j]);
                float v2r = 0.5f * (z2r[j] + zrB[j]);
                float v2i = 0.5f * (z2i[j] - ziB[j]);
                g_Wc[((size_t)j * M_TOT + m1) * 96 + dp] =
                    make_float2(v1r - v2i, v1i + v2r);
                // W[N-k]: V1' = (z' + conj(z))/2 = (v1r, -v1i); V2' = (v2r, -v2i)
                g_Wc[((size_t)j * M_TOT + m2) * 96 + dp] =
                    make_float2(v1r + v2i, -v1i + v2r);
            }
        }
    }
}

// ============================================================================
// K7: inverse FFT-4096 on packed hermitian columns; both outputs real.
// CTA = (b, blk, 4 channel-pairs) -> 8 output channels.
// ============================================================================
__global__ __launch_bounds__(FFT_THREADS, 1) void fft_n_inv(float* __restrict__ out) {
    extern __shared__ float sm[];
    float* sr = sm;
    float* si = sm + 4 * N_DIM;
    float2* tw = (float2*)(sm + 8 * N_DIM);
    const int b   = blockIdx.x / 96;
    const int r8  = blockIdx.x % 96;
    const int blk = r8 / 24;
    const int dp0 = (r8 % 24) * 4;
    const int tid = threadIdx.x;

    for (int k = tid; k < N_DIM; k += FFT_THREADS) {
        const float2* wp = g_Wc + ((size_t)blk * M_TOT + b * N_DIM + k) * 96 + dp0;
        float2 w0 = wp[0], w1 = wp[1], w2 = wp[2], w3 = wp[3];
        int r = __brev((unsigned)k) >> 20;
        sr[0 * N_DIM + r] = w0.x;  si[0 * N_DIM + r] = w0.y;
        sr[1 * N_DIM + r] = w1.x;  si[1 * N_DIM + r] = w1.y;
        sr[2 * N_DIM + r] = w2.x;  si[2 * N_DIM + r] = w2.y;
        sr[3 * N_DIM + r] = w3.x;  si[3 * N_DIM + r] = w3.y;
    }
    __syncthreads();
    fft_core<+1>(sr, si, tw, tid);

    const int cbase = blk * BS + 2 * dp0;
    for (int n = tid; n < N_DIM; n += FFT_THREADS) {
        float4 o0 = make_float4(sr[n] * INV128,           si[n] * INV128,
                                sr[N_DIM + n] * INV128,   si[N_DIM + n] * INV128);
        float4 o1 = make_float4(sr[2 * N_DIM + n] * INV128, si[2 * N_DIM + n] * INV128,
                                sr[3 * N_DIM + n] * INV128, si[3 * N_DIM + n] * INV128);
        float* op = &out[((size_t)(b * N_DIM + n)) * C_DIM + cbase];
        *(float4*)op       = o0;
        *(float4*)(op + 4) = o1;
    }
}

// ============================================================================
// launch
// ============================================================================
extern "C" void kernel_launch(void* const* d_in, const int* in_sizes, int n_in,
                              void* d_out, int out_size) {
    (void)in_sizes; (void)n_in; (void)out_size;
    const float* x  = (const float*)d_in[0];
    const float* w1 = (const float*)d_in[1];
    const float* b1 = (const float*)d_in[2];
    const float* w2 = (const float*)d_in[3];
    const float* b2 = (const float*)d_in[4];
    float* out = (float*)d_out;

    cudaFuncSetAttribute(fft_n_fwd, cudaFuncAttributeMaxDynamicSharedMemorySize, FFT_SMEM);
    cudaFuncSetAttribute(fft_n_inv, cudaFuncAttributeMaxDynamicSharedMemorySize, FFT_SMEM);
    cudaFuncSetAttribute(gemm_mma<1>, cudaFuncAttributeMaxDynamicSharedMemorySize, GEMM_SMEM);
    cudaFuncSetAttribute(gemm_mma<2>, cudaFuncAttributeMaxDynamicSharedMemorySize, GEMM_SMEM);

    fft_n_fwd<<<B_DIM * 96, FFT_THREADS, FFT_SMEM>>>(x);
    fft4_pack<<<(M_TOT * BS) / 256, 256>>>();
    prep_weights<<<(NB * KS * GK + 255) / 256, 256>>>(w1, b1, w2, b2);

    dim3 gg(3, M_TOT / 128, NB);
    gemm_mma<1><<<gg, 256, GEMM_SMEM>>>();
    gemm_mma<2><<<gg, 256, GEMM_SMEM>>>();

    ifft4_wpack<<<(B_DIM * 2049 * 96 + 255) / 256, 256>>>();
    fft_n_inv<<<B_DIM * 96, FFT_THREADS, FFT_SMEM>>>(out);
}

// round 9
// speedup vs baseline: 1.9658x; 1.1307x over previous
#include <cuda_runtime.h>
#include <cuda_bf16.h>
#include <cstdint>

// ============================================================================
// EinFFT (sm_103) — HMMA bf16x3 GEMM (3-stage, 2 CTAs/SM) + paired-real fwd FFT
//   + hermitian-packed inverse FFT
// ============================================================================

#define B_DIM 8
#define N_DIM 4096
#define C_DIM 768
#define BS    192
#define NB    4
#define M_TOT (B_DIM * N_DIM)      // 32768
#define KS    384                  // stacked [re|im]
#define GK    768                  // stored K: [hi(384) | lo(384)]
#define KCH   18                   // K chunks of 64 (effective K = 1152)
#define LAMBDA 0.01f
#define INV128 (1.0f / 128.0f)

#define FFT_THREADS 1024
#define FFT_SMEM ((8 * N_DIM + 2 * N_DIM) * 4)   // 128KB data + 32KB twiddle
#define STAGE_BYTES 32768                        // A 16KB + B 16KB per stage
#define NSTG 3
#define GEMM_SMEM (NSTG * STAGE_BYTES)           // 98304 -> 2 CTAs/SM

// -------- scratch (static device globals; no runtime allocation) ------------
static __device__ float          g_Fr [(size_t)B_DIM * N_DIM * C_DIM];
static __device__ float          g_Fi [(size_t)B_DIM * N_DIM * C_DIM];
static __device__ unsigned short g_Xb [(size_t)NB * M_TOT * GK];   // bf16 [hi|lo]
static __device__ unsigned short g_Hb [(size_t)NB * M_TOT * GK];   // bf16 [hi|lo]
static __device__ unsigned short g_W1b[(size_t)NB * KS * GK];      // Wt bf16 [hi|lo]
static __device__ unsigned short g_W2b[(size_t)NB * KS * GK];
static __device__ float          g_B1 [NB * KS];
static __device__ float          g_B2 [NB * KS];
static __device__ float          g_P  [(size_t)NB * M_TOT * KS];   // fp32 MLP out
static __device__ float2         g_Wc [(size_t)NB * M_TOT * 96];   // packed herm spectrum

// ============================================================================
// helpers (arch-neutral PTX only)
// ============================================================================
__device__ __forceinline__ uint32_t smem_u32(const void* p) {
    uint32_t a;
    asm("{ .reg .u64 t; cvta.to.shared.u64 t, %1; cvt.u32.u64 %0, t; }"
        : "=r"(a) : "l"(p));
    return a;
}
__device__ __forceinline__ uint32_t swz128(uint32_t off) {
    return off ^ ((off >> 3) & 0x70);
}
__device__ __forceinline__ void cp16(uint32_t s, const void* g) {
    asm volatile("cp.async.cg.shared.global [%0], [%1], 16;" :: "r"(s), "l"(g));
}
__device__ __forceinline__ void ldsm_x4(uint32_t* r, uint32_t addr) {
    asm volatile("ldmatrix.sync.aligned.m8n8.x4.shared.b16 {%0,%1,%2,%3}, [%4];"
        : "=r"(r[0]), "=r"(r[1]), "=r"(r[2]), "=r"(r[3]) : "r"(addr));
}
__device__ __forceinline__ void mma16816(float* c, const uint32_t* a,
                                         uint32_t b0, uint32_t b1) {
    asm volatile(
        "mma.sync.aligned.m16n8k16.row.col.f32.bf16.bf16.f32 "
        "{%0,%1,%2,%3}, {%4,%5,%6,%7}, {%8,%9}, {%0,%1,%2,%3};"
        : "+f"(c[0]), "+f"(c[1]), "+f"(c[2]), "+f"(c[3])
        : "r"(a[0]), "r"(a[1]), "r"(a[2]), "r"(a[3]), "r"(b0), "r"(b1));
}

// chunk c -> (A k-offset, W k-offset). [0,6): hi*hi; [6,12): a_hi*w_lo; [12,18): a_lo*w_hi
__device__ __forceinline__ void chunk_offsets(int c, int& aoff, int& boff) {
    if (c < 6)       { aoff = c * 64;              boff = c * 64; }
    else if (c < 12) { aoff = (c - 6) * 64;        boff = 384 + (c - 6) * 64; }
    else             { aoff = 384 + (c - 12) * 64; boff = (c - 12) * 64; }
}

__device__ __forceinline__ void load_chunk(const unsigned short* __restrict__ A,
                                           const unsigned short* __restrict__ W,
                                           uint32_t sA, uint32_t sB,
                                           int aoff, int boff, int tid) {
    #pragma unroll
    for (int t = 0; t < 4; t++) {
        int idx = tid + t * 256;
        int r = idx >> 3, i = idx & 7;
        cp16(sA + swz128((uint32_t)(r * 128 + i * 16)),
             A + (size_t)r * GK + aoff + i * 8);
    }
    #pragma unroll
    for (int t = 0; t < 4; t++) {
        int idx = tid + t * 256;
        int r = idx >> 3, i = idx & 7;
        cp16(sB + swz128((uint32_t)(r * 128 + i * 16)),
             W + (size_t)r * GK + boff + i * 8);
    }
    asm volatile("cp.async.commit_group;" ::: "memory");
}

// ============================================================================
// FFT-4096 core (radix-2 DIT, smem, stage-contiguous twiddle table; 4 columns)
// ============================================================================
template <int DIR>   // -1 forward, +1 inverse
static __device__ __forceinline__ void fft_core(float* sr, float* si, float2* tw, int tid) {
    for (int j = tid; j < N_DIM - 1; j += FFT_THREADS) {
        int half = 1 << (31 - __clz(j + 1));
        int pos  = (j + 1) - half;
        float s, c;
        __sincosf(-3.14159265358979f * (float)pos / (float)half, &s, &c);
        tw[j] = make_float2(c, s);
    }
    __syncthreads();
    for (int len = 2; len <= N_DIM; len <<= 1) {
        const int half = len >> 1;
        for (int idx = tid; idx < 4 * (N_DIM / 2); idx += FFT_THREADS) {
            const int col = idx >> 11;
            const int j   = idx & (N_DIM / 2 - 1);
            const int pos = j & (half - 1);
            const int i0  = ((j - pos) << 1) + pos;
            const int i1  = i0 + half;
            float2 t = tw[half - 1 + pos];
            float c = t.x;
            float s = (DIR < 0) ? t.y : -t.y;
            float* pr = sr + col * N_DIM;
            float* pi = si + col * N_DIM;
            float xr = pr[i1], xi = pi[i1];
            float vr = xr * c - xi * s;
            float vi = xr * s + xi * c;
            float ur = pr[i0], ui = pi[i0];
            pr[i0] = ur + vr;  pi[i0] = ui + vi;
            pr[i1] = ur - vr;  pi[i1] = ui - vi;
        }
        __syncthreads();
    }
}

// ============================================================================
// K1: forward FFT-4096, paired-real. One CTA = 8 channels as 4 complex cols.
// ============================================================================
__global__ __launch_bounds__(FFT_THREADS, 1) void fft_n_fwd(const float* __restrict__ x) {
    extern __shared__ float sm[];
    float* sr = sm;
    float* si = sm + 4 * N_DIM;
    float2* tw = (float2*)(sm + 8 * N_DIM);
    const int b  = blockIdx.x / 96;
    const int c0 = (blockIdx.x % 96) * 8;
    const int tid = threadIdx.x;

    for (int n = tid; n < N_DIM; n += FFT_THREADS) {
        const float* row = &x[((size_t)(b * N_DIM + n)) * C_DIM + c0];
        float4 v0 = *(const float4*)row;
        float4 v1 = *(const float4*)(row + 4);
        int r = __brev((unsigned)n) >> 20;
        sr[0 * N_DIM + r] = v0.x;  si[0 * N_DIM + r] = v0.y;
        sr[1 * N_DIM + r] = v0.z;  si[1 * N_DIM + r] = v0.w;
        sr[2 * N_DIM + r] = v1.x;  si[2 * N_DIM + r] = v1.y;
        sr[3 * N_DIM + r] = v1.z;  si[3 * N_DIM + r] = v1.w;
    }
    __syncthreads();
    fft_core<-1>(sr, si, tw, tid);

    for (int k = tid; k < N_DIM; k += FFT_THREADS) {
        const int kr = (N_DIM - k) & (N_DIM - 1);
        float fr[8], fi[8];
        #pragma unroll
        for (int t = 0; t < 4; t++) {
            float pr = sr[t * N_DIM + k],  pi_ = si[t * N_DIM + k];
            float qr = sr[t * N_DIM + kr], qi  = si[t * N_DIM + kr];
            fr[2 * t]     = 0.5f * (pr + qr);
            fi[2 * t]     = 0.5f * (pi_ - qi);
            fr[2 * t + 1] = 0.5f * (pi_ + qi);
            fi[2 * t + 1] = 0.5f * (qr - pr);
        }
        size_t o = ((size_t)(b * N_DIM + k)) * C_DIM + c0;
        *(float4*)&g_Fr[o]     = *(float4*)&fr[0];
        *(float4*)&g_Fr[o + 4] = *(float4*)&fr[4];
        *(float4*)&g_Fi[o]     = *(float4*)&fi[0];
        *(float4*)&g_Fi[o + 4] = *(float4*)&fi[4];
    }
}

// ============================================================================
// K2: FFT-4 along block axis + 1/128 scale, pack bf16 hi/lo GEMM rows.
// ============================================================================
__global__ void fft4_pack() {
    int idx = blockIdx.x * blockDim.x + threadIdx.x;
    if (idx >= M_TOT * BS) return;
    const int m = idx / BS;
    const int d = idx % BS;

    const size_t base = (size_t)m * C_DIM + d;
    float xr0 = g_Fr[base],          xi0 = g_Fi[base];
    float xr1 = g_Fr[base + BS],     xi1 = g_Fi[base + BS];
    float xr2 = g_Fr[base + 2 * BS], xi2 = g_Fi[base + 2 * BS];
    float xr3 = g_Fr[base + 3 * BS], xi3 = g_Fi[base + 3 * BS];

    float yr[4], yi[4];
    yr[0] = (xr0 + xr1 + xr2 + xr3) * INV128;  yi[0] = (xi0 + xi1 + xi2 + xi3) * INV128;
    yr[1] = (xr0 + xi1 - xr2 - xi3) * INV128;  yi[1] = (xi0 - xr1 - xi2 + xr3) * INV128;
    yr[2] = (xr0 - xr1 + xr2 - xr3) * INV128;  yi[2] = (xi0 - xi1 + xi2 - xi3) * INV128;
    yr[3] = (xr0 - xi1 - xr2 + xi3) * INV128;  yi[3] = (xi0 + xr1 - xi2 - xr3) * INV128;

    const size_t PLX = (size_t)M_TOT * GK;
    #pragma unroll
    for (int p = 0; p < 4; p++) {
        unsigned short* row = g_Xb + p * PLX + (size_t)m * GK;
        __nv_bfloat16 hr = __float2bfloat16(yr[p]);
        __nv_bfloat16 hi = __float2bfloat16(yi[p]);
        row[d]            = __bfloat16_as_ushort(hr);
        row[BS + d]       = __bfloat16_as_ushort(hi);
        row[KS + d]       = __bfloat16_as_ushort(__float2bfloat16(yr[p] - __bfloat162float(hr)));
        row[KS + BS + d]  = __bfloat16_as_ushort(__float2bfloat16(yi[p] - __bfloat162float(hi)));
    }
}

// ============================================================================
// K3: stacked weights, transposed + bf16 hi/lo.  Ws = [[Wr, Wi], [-Wi, Wr]]
// ============================================================================
__global__ void prep_weights(const float* __restrict__ w1, const float* __restrict__ b1,
                             const float* __restrict__ w2, const float* __restrict__ b2) {
    int idx = blockIdx.x * blockDim.x + threadIdx.x;
    if (idx < NB * KS * GK) {
        int k   = idx % GK;
        int n   = (idx / GK) % KS;
        int blk = idx / (GK * KS);
        int kk  = (k >= KS) ? k - KS : k;
        bool lohalf = (k >= KS);
        int dd = (kk < BS) ? kk : kk - BS;
        int cc = (n  < BS) ? n  : n  - BS;
        bool rlo = kk < BS, clo = n < BS;
        size_t ir = ((size_t)blk        * BS + dd) * BS + cc;
        size_t ii = ((size_t)(NB + blk) * BS + dd) * BS + cc;
        float v1, v2;
        if (rlo == clo) { v1 =  w1[ir]; v2 =  w2[ir]; }
        else if (rlo)   { v1 =  w1[ii]; v2 =  w2[ii]; }
        else            { v1 = -w1[ii]; v2 = -w2[ii]; }
        __nv_bfloat16 h1 = __float2bfloat16(v1);
        __nv_bfloat16 h2 = __float2bfloat16(v2);
        if (lohalf) {
            g_W1b[idx] = __bfloat16_as_ushort(__float2bfloat16(v1 - __bfloat162float(h1)));
            g_W2b[idx] = __bfloat16_as_ushort(__float2bfloat16(v2 - __bfloat162float(h2)));
        } else {
            g_W1b[idx] = __bfloat16_as_ushort(h1);
            g_W2b[idx] = __bfloat16_as_ushort(h2);
        }
    }
    if (idx < NB * KS) {
        int blk = idx / KS;
        int c   = idx % KS;
        size_t ib = (c < BS) ? ((size_t)blk * BS + c)
                             : ((size_t)(NB + blk) * BS + (c - BS));
        g_B1[idx] = b1[ib];
        g_B2[idx] = b2[ib];
    }
}

// ============================================================================
// K4/K5: HMMA bf16x3 GEMM. CTA 128x128, 8 warps (4x2), warp tile 32x64.
// 3-stage cp.async pipeline (prefetch distance 2), 2 CTAs/SM for cross-CTA
// latency hiding. Single-buffered fragments to fit 128 regs.
// ============================================================================
template <int LAYER>
__global__ __launch_bounds__(256, 2) void gemm_mma() {
    extern __shared__ __align__(1024) char smem_raw[];
    const uint32_t smem = smem_u32(smem_raw);
    const int tid    = threadIdx.x;
    const int wid    = tid >> 5;
    const int lane   = tid & 31;
    const int warp_m = wid & 3;
    const int warp_n = wid >> 2;
    const int n0     = blockIdx.x * 128;
    const int tile_m = blockIdx.y * 128;
    const int blk    = blockIdx.z;

    const unsigned short* A = (LAYER == 1 ? g_Xb : g_Hb)
                            + (size_t)blk * M_TOT * GK + (size_t)tile_m * GK;
    const unsigned short* W = (LAYER == 1 ? g_W1b : g_W2b)
                            + (size_t)blk * KS * GK + (size_t)n0 * GK;
    const float* bias       = (LAYER == 1 ? g_B1 : g_B2) + blk * KS;

    float acc[2][8][4];
    #pragma unroll
    for (int i = 0; i < 2; i++)
        #pragma unroll
        for (int j = 0; j < 8; j++)
            #pragma unroll
            for (int q = 0; q < 4; q++) acc[i][j][q] = 0.f;

    // prologue: chunks 0,1 into stages 0,1
    #pragma unroll
    for (int c = 0; c < 2; c++) {
        int ao, bo; chunk_offsets(c, ao, bo);
        uint32_t sA = smem + c * STAGE_BYTES;
        load_chunk(A, W, sA, sA + 16384, ao, bo, tid);
    }

    const uint32_t a_row = (uint32_t)(warp_m * 32 + (lane & 15));
    const uint32_t a_cb  = (uint32_t)((lane >> 4) * 16);
    const uint32_t b_row = (uint32_t)(warp_n * 64 + (lane & 7) + ((lane >> 4) * 8));
    const uint32_t b_cb  = (uint32_t)(((lane >> 3) & 1) * 16);

    for (int c = 0; c < KCH; c++) {
        if (c + 1 < KCH) asm volatile("cp.async.wait_group 1;" ::: "memory");
        else             asm volatile("cp.async.wait_group 0;" ::: "memory");
        __syncthreads();   // reads of chunk c-1 (stage (c+2)%3) retired

        if (c + 2 < KCH) {
            int ao, bo; chunk_offsets(c + 2, ao, bo);
            uint32_t sL = smem + ((c + 2) % NSTG) * STAGE_BYTES;
            load_chunk(A, W, sL, sL + 16384, ao, bo, tid);
        }

        const uint32_t sA = smem + (c % NSTG) * STAGE_BYTES;
        const uint32_t sB = sA + 16384;

        #pragma unroll
        for (int k16 = 0; k16 < 4; k16++) {
            uint32_t af[2][4], bf[4][4];
            #pragma unroll
            for (int mi = 0; mi < 2; mi++)
                ldsm_x4(af[mi], sA + swz128((a_row + mi * 16) * 128 + k16 * 32 + a_cb));
            #pragma unroll
            for (int nj = 0; nj < 4; nj++)
                ldsm_x4(bf[nj], sB + swz128((b_row + nj * 16) * 128 + k16 * 32 + b_cb));
            #pragma unroll
            for (int mi = 0; mi < 2; mi++)
                #pragma unroll
                for (int nj = 0; nj < 4; nj++) {
                    mma16816(acc[mi][2 * nj],     af[mi], bf[nj][0], bf[nj][1]);
                    mma16816(acc[mi][2 * nj + 1], af[mi], bf[nj][2], bf[nj][3]);
                }
        }
    }

    // epilogue
    #pragma unroll
    for (int mi = 0; mi < 2; mi++) {
        #pragma unroll
        for (int na = 0; na < 8; na++) {
            const int col  = n0 + warp_n * 64 + na * 8 + 2 * (lane & 3);
            const int row0 = tile_m + warp_m * 32 + mi * 16 + (lane >> 2);
            const float b0 = bias[col], b1 = bias[col + 1];
            #pragma unroll
            for (int h = 0; h < 2; h++) {
                const int row = row0 + h * 8;
                float v0 = acc[mi][na][2 * h]     + b0;
                float v1 = acc[mi][na][2 * h + 1] + b1;
                if (LAYER == 1) {
                    v0 = fmaxf(v0, 0.f);
                    v1 = fmaxf(v1, 0.f);
                    __nv_bfloat16 h0 = __float2bfloat16(v0);
                    __nv_bfloat16 h1 = __float2bfloat16(v1);
                    ushort2 hs = make_ushort2(__bfloat16_as_ushort(h0),
                                              __bfloat16_as_ushort(h1));
                    ushort2 ls = make_ushort2(
                        __bfloat16_as_ushort(__float2bfloat16(v0 - __bfloat162float(h0))),
                        __bfloat16_as_ushort(__float2bfloat16(v1 - __bfloat162float(h1))));
                    unsigned short* rb = g_Hb + ((size_t)blk * M_TOT + row) * GK;
                    *(ushort2*)(rb + col)      = hs;
                    *(ushort2*)(rb + KS + col) = ls;
                } else {
                    v0 = (v0 > LAMBDA) ? v0 - LAMBDA
                                       : ((v0 < -LAMBDA) ? v0 + LAMBDA : 0.f);
                    v1 = (v1 > LAMBDA) ? v1 - LAMBDA
                                       : ((v1 < -LAMBDA) ? v1 + LAMBDA : 0.f);
                    *(float2*)(g_P + ((size_t)blk * M_TOT + row) * KS + col)
                        = make_float2(v0, v1);
                }
            }
        }
    }
}

// ============================================================================
// K6: inverse FFT-4 along block axis + hermitian channel-pair packing.
// ============================================================================
__global__ void ifft4_wpack() {
    const int idx = blockIdx.x * blockDim.x + threadIdx.x;
    const int total = B_DIM * 2049 * 96;
    if (idx >= total) return;
    const int dp   = idx % 96;
    const int kpos = (idx / 96) % 2049;
    const int b    = idx / (96 * 2049);
    const int d    = 2 * dp;
    const int m1   = b * N_DIM + kpos;
    const int m2   = b * N_DIM + ((N_DIM - kpos) & (N_DIM - 1));

    const size_t PL = (size_t)M_TOT * KS;

    float z1r[4], z1i[4], z2r[4], z2i[4];
    #pragma unroll
    for (int rowsel = 0; rowsel < 2; rowsel++) {
        const int m = rowsel ? m2 : m1;
        float yrA[4], yiA[4], yrB[4], yiB[4];
        #pragma unroll
        for (int k2 = 0; k2 < 4; k2++) {
            const float* pp = g_P + k2 * PL + (size_t)m * KS;
            float2 re = *(const float2*)(pp + d);
            float2 im = *(const float2*)(pp + BS + d);
            yrA[k2] = re.x;  yrB[k2] = re.y;
            yiA[k2] = im.x;  yiB[k2] = im.y;
        }
        float zrA[4], ziA[4], zrB[4], ziB[4];
        zrA[0] = yrA[0] + yrA[1] + yrA[2] + yrA[3];
        ziA[0] = yiA[0] + yiA[1] + yiA[2] + yiA[3];
        zrA[1] = yrA[0] - yiA[1] - yrA[2] + yiA[3];
        ziA[1] = yiA[0] + yrA[1] - yiA[2] - yrA[3];
        zrA[2] = yrA[0] - yrA[1] + yrA[2] - yrA[3];
        ziA[2] = yiA[0] - yiA[1] + yiA[2] - yiA[3];
        zrA[3] = yrA[0] + yiA[1] - yrA[2] - yiA[3];
        ziA[3] = yiA[0] - yrA[1] - yiA[2] + yrA[3];
        zrB[0] = yrB[0] + yrB[1] + yrB[2] + yrB[3];
        ziB[0] = yiB[0] + yiB[1] + yiB[2] + yiB[3];
        zrB[1] = yrB[0] - yiB[1] - yrB[2] + yiB[3];
        ziB[1] = yiB[0] + yrB[1] - yiB[2] - yrB[3];
        zrB[2] = yrB[0] - yrB[1] + yrB[2] - yrB[3];
        ziB[2] = yiB[0] - yiB[1] + yiB[2] - yiB[3];
        zrB[3] = yrB[0] + yiB[1] - yrB[2] - yiB[3];
        ziB[3] = yiB[0] - yrB[1] - yiB[2] + yrB[3];
        if (rowsel == 0) {
            #pragma unroll
            for (int j = 0; j < 4; j++) {
                z1r[j] = zrA[j]; z1i[j] = ziA[j];
                z2r[j] = zrB[j]; z2i[j] = ziB[j];
            }
        } else {
            #pragma unroll
            for (int j = 0; j < 4; j++) {
                float v1r = 0.5f * (z1r[j] + zrA[j]);
                float v1i = 0.5f * (z1i[j] - ziA[j]);
                float v2r = 0.5f * (z2r[j] + zrB[j]);
                float v2i = 0.5f * (z2i[j] - ziB[j]);
                g_Wc[((size_t)j * M_TOT + m1) * 96 + dp] =
                    make_float2(v1r - v2i, v1i + v2r);
                g_Wc[((size_t)j * M_TOT + m2) * 96 + dp] =
                    make_float2(v1r + v2i, -v1i + v2r);
            }
        }
    }
}

// ============================================================================
// K7: inverse FFT-4096 on packed hermitian columns; both outputs real.
// ============================================================================
__global__ __launch_bounds__(FFT_THREADS, 1) void fft_n_inv(float* __restrict__ out) {
    extern __shared__ float sm[];
    float* sr = sm;
    float* si = sm + 4 * N_DIM;
    float2* tw = (float2*)(sm + 8 * N_DIM);
    const int b   = blockIdx.x / 96;
    const int r8  = blockIdx.x % 96;
    const int blk = r8 / 24;
    const int dp0 = (r8 % 24) * 4;
    const int tid = threadIdx.x;

    for (int k = tid; k < N_DIM; k += FFT_THREADS) {
        const float2* wp = g_Wc + ((size_t)blk * M_TOT + b * N_DIM + k) * 96 + dp0;
        float2 w0 = wp[0], w1 = wp[1], w2 = wp[2], w3 = wp[3];
        int r = __brev((unsigned)k) >> 20;
        sr[0 * N_DIM + r] = w0.x;  si[0 * N_DIM + r] = w0.y;
        sr[1 * N_DIM + r] = w1.x;  si[1 * N_DIM + r] = w1.y;
        sr[2 * N_DIM + r] = w2.x;  si[2 * N_DIM + r] = w2.y;
        sr[3 * N_DIM + r] = w3.x;  si[3 * N_DIM + r] = w3.y;
    }
    __syncthreads();
    fft_core<+1>(sr, si, tw, tid);

    const int cbase = blk * BS + 2 * dp0;
    for (int n = tid; n < N_DIM; n += FFT_THREADS) {
        float4 o0 = make_float4(sr[n] * INV128,           si[n] * INV128,
                                sr[N_DIM + n] * INV128,   si[N_DIM + n] * INV128);
        float4 o1 = make_float4(sr[2 * N_DIM + n] * INV128, si[2 * N_DIM + n] * INV128,
                                sr[3 * N_DIM + n] * INV128, si[3 * N_DIM + n] * INV128);
        float* op = &out[((size_t)(b * N_DIM + n)) * C_DIM + cbase];
        *(float4*)op       = o0;
        *(float4*)(op + 4) = o1;
    }
}

// ============================================================================
// launch
// ============================================================================
extern "C" void kernel_launch(void* const* d_in, const int* in_sizes, int n_in,
                              void* d_out, int out_size) {
    (void)in_sizes; (void)n_in; (void)out_size;
    const float* x  = (const float*)d_in[0];
    const float* w1 = (const float*)d_in[1];
    const float* b1 = (const float*)d_in[2];
    const float* w2 = (const float*)d_in[3];
    const float* b2 = (const float*)d_in[4];
    float* out = (float*)d_out;

    cudaFuncSetAttribute(fft_n_fwd, cudaFuncAttributeMaxDynamicSharedMemorySize, FFT_SMEM);
    cudaFuncSetAttribute(fft_n_inv, cudaFuncAttributeMaxDynamicSharedMemorySize, FFT_SMEM);
    cudaFuncSetAttribute(gemm_mma<1>, cudaFuncAttributeMaxDynamicSharedMemorySize, GEMM_SMEM);
    cudaFuncSetAttribute(gemm_mma<2>, cudaFuncAttributeMaxDynamicSharedMemorySize, GEMM_SMEM);

    fft_n_fwd<<<B_DIM * 96, FFT_THREADS, FFT_SMEM>>>(x);
    fft4_pack<<<(M_TOT * BS) / 256, 256>>>();
    prep_weights<<<(NB * KS * GK + 255) / 256, 256>>>(w1, b1, w2, b2);

    dim3 gg(3, M_TOT / 128, NB);
    gemm_mma<1><<<gg, 256, GEMM_SMEM>>>();
    gemm_mma<2><<<gg, 256, GEMM_SMEM>>>();

    ifft4_wpack<<<(B_DIM * 2049 * 96 + 255) / 256, 256>>>();
    fft_n_inv<<<B_DIM * 96, FFT_THREADS, FFT_SMEM>>>(out);
}

// round 10
// speedup vs baseline: 2.3490x; 1.1950x over previous
#include <cuda_runtime.h>
#include <cuda_bf16.h>
#include <cstdint>

// ============================================================================
// EinFFT (sm_103) — HMMA bf16x3 GEMM (3-stage, 2 CTAs/SM)
//   + radix-4 paired-real fwd FFT + radix-4 hermitian-packed inverse FFT
// ============================================================================

#define B_DIM 8
#define N_DIM 4096
#define C_DIM 768
#define BS    192
#define NB    4
#define M_TOT (B_DIM * N_DIM)      // 32768
#define KS    384                  // stacked [re|im]
#define GK    768                  // stored K: [hi(384) | lo(384)]
#define KCH   18                   // K chunks of 64 (effective K = 1152)
#define LAMBDA 0.01f
#define INV128 (1.0f / 128.0f)

#define FFT_THREADS 1024
#define FFT_SMEM ((4 * N_DIM + 1376) * 8)        // float2: 128KB data + 11KB twiddle
#define STAGE_BYTES 32768                        // A 16KB + B 16KB per stage
#define NSTG 3
#define GEMM_SMEM (NSTG * STAGE_BYTES)           // 98304 -> 2 CTAs/SM

// -------- scratch (static device globals; no runtime allocation) ------------
static __device__ float          g_Fr [(size_t)B_DIM * N_DIM * C_DIM];
static __device__ float          g_Fi [(size_t)B_DIM * N_DIM * C_DIM];
static __device__ unsigned short g_Xb [(size_t)NB * M_TOT * GK];   // bf16 [hi|lo]
static __device__ unsigned short g_Hb [(size_t)NB * M_TOT * GK];   // bf16 [hi|lo]
static __device__ unsigned short g_W1b[(size_t)NB * KS * GK];      // Wt bf16 [hi|lo]
static __device__ unsigned short g_W2b[(size_t)NB * KS * GK];
static __device__ float          g_B1 [NB * KS];
static __device__ float          g_B2 [NB * KS];
static __device__ float          g_P  [(size_t)NB * M_TOT * KS];   // fp32 MLP out
static __device__ float2         g_Wc [(size_t)NB * M_TOT * 96];   // packed herm spectrum

// ============================================================================
// helpers (arch-neutral PTX only)
// ============================================================================
__device__ __forceinline__ uint32_t smem_u32(const void* p) {
    uint32_t a;
    asm("{ .reg .u64 t; cvta.to.shared.u64 t, %1; cvt.u32.u64 %0, t; }"
        : "=r"(a) : "l"(p));
    return a;
}
__device__ __forceinline__ uint32_t swz128(uint32_t off) {
    return off ^ ((off >> 3) & 0x70);
}
__device__ __forceinline__ void cp16(uint32_t s, const void* g) {
    asm volatile("cp.async.cg.shared.global [%0], [%1], 16;" :: "r"(s), "l"(g));
}
__device__ __forceinline__ void ldsm_x4(uint32_t* r, uint32_t addr) {
    asm volatile("ldmatrix.sync.aligned.m8n8.x4.shared.b16 {%0,%1,%2,%3}, [%4];"
        : "=r"(r[0]), "=r"(r[1]), "=r"(r[2]), "=r"(r[3]) : "r"(addr));
}
__device__ __forceinline__ void mma16816(float* c, const uint32_t* a,
                                         uint32_t b0, uint32_t b1) {
    asm volatile(
        "mma.sync.aligned.m16n8k16.row.col.f32.bf16.bf16.f32 "
        "{%0,%1,%2,%3}, {%4,%5,%6,%7}, {%8,%9}, {%0,%1,%2,%3};"
        : "+f"(c[0]), "+f"(c[1]), "+f"(c[2]), "+f"(c[3])
        : "r"(a[0]), "r"(a[1]), "r"(a[2]), "r"(a[3]), "r"(b0), "r"(b1));
}
__device__ __forceinline__ float2 cmul(float2 a, float2 b) {
    return make_float2(a.x * b.x - a.y * b.y, a.x * b.y + a.y * b.x);
}

// chunk c -> (A k-offset, W k-offset). [0,6): hi*hi; [6,12): a_hi*w_lo; [12,18): a_lo*w_hi
__device__ __forceinline__ void chunk_offsets(int c, int& aoff, int& boff) {
    if (c < 6)       { aoff = c * 64;              boff = c * 64; }
    else if (c < 12) { aoff = (c - 6) * 64;        boff = 384 + (c - 6) * 64; }
    else             { aoff = 384 + (c - 12) * 64; boff = (c - 12) * 64; }
}

__device__ __forceinline__ void load_chunk(const unsigned short* __restrict__ A,
                                           const unsigned short* __restrict__ W,
                                           uint32_t sA, uint32_t sB,
                                           int aoff, int boff, int tid) {
    #pragma unroll
    for (int t = 0; t < 4; t++) {
        int idx = tid + t * 256;
        int r = idx >> 3, i = idx & 7;
        cp16(sA + swz128((uint32_t)(r * 128 + i * 16)),
             A + (size_t)r * GK + aoff + i * 8);
    }
    #pragma unroll
    for (int t = 0; t < 4; t++) {
        int idx = tid + t * 256;
        int r = idx >> 3, i = idx & 7;
        cp16(sB + swz128((uint32_t)(r * 128 + i * 16)),
             W + (size_t)r * GK + boff + i * 8);
    }
    asm volatile("cp.async.commit_group;" ::: "memory");
}

// base-4 digit reversal of a 12-bit index
__device__ __forceinline__ int rev4(unsigned n) {
    unsigned r2 = __brev(n) >> 20;
    return (int)(((r2 & 0x555u) << 1) | ((r2 >> 1) & 0x555u));
}

// ============================================================================
// Radix-4 FFT-4096 core: 4 complex columns (float2), 6 stages, twiddle table.
// Caller loads data (digit-reversed positions); core fills table, syncs, runs.
// ============================================================================
template <int DIR>   // -1 forward, +1 inverse
static __device__ __forceinline__ void fft4_core(float2* s, float2* tw, int tid) {
    // twiddle table: stage s (quarter q): tw[off+p] = exp(-2*pi*i*p/(4q))
    {
        int off = 0, q = 1;
        #pragma unroll
        for (int st = 0; st < 6; st++) {
            for (int p = tid; p < q; p += FFT_THREADS) {
                float sn, cs;
                __sincosf(-6.283185307179586f * (float)p / (float)(4 * q), &sn, &cs);
                tw[off + p] = make_float2(cs, sn);
            }
            off += q; q <<= 2;
        }
    }
    __syncthreads();

    int off = 0, q = 1;
    #pragma unroll
    for (int st = 0; st < 6; st++) {
        for (int it = tid; it < 4 * (N_DIM / 4); it += FFT_THREADS) {
            const int col = it >> 10;
            const int j   = it & (N_DIM / 4 - 1);
            const int pos = j & (q - 1);
            float2* p0 = s + col * N_DIM + ((j - pos) << 2) + pos;

            float2 w1 = tw[off + pos];
            if (DIR > 0) w1.y = -w1.y;
            float2 w2 = cmul(w1, w1);
            float2 w3 = cmul(w2, w1);

            float2 a  = p0[0];
            float2 b  = cmul(p0[q],     w1);
            float2 c2 = cmul(p0[2 * q], w2);
            float2 d  = cmul(p0[3 * q], w3);

            float2 t0 = make_float2(a.x + c2.x, a.y + c2.y);
            float2 t1 = make_float2(a.x - c2.x, a.y - c2.y);
            float2 t2 = make_float2(b.x + d.x,  b.y + d.y);
            float2 t3 = make_float2(b.x - d.x,  b.y - d.y);
            // forward: t3 * (-i) ; inverse: t3 * (+i)
            float2 t3r = (DIR < 0) ? make_float2(t3.y, -t3.x)
                                   : make_float2(-t3.y, t3.x);

            p0[0]     = make_float2(t0.x + t2.x,  t0.y + t2.y);
            p0[q]     = make_float2(t1.x + t3r.x, t1.y + t3r.y);
            p0[2 * q] = make_float2(t0.x - t2.x,  t0.y - t2.y);
            p0[3 * q] = make_float2(t1.x - t3r.x, t1.y - t3r.y);
        }
        __syncthreads();
        off += q; q <<= 2;
    }
}

// ============================================================================
// K1: forward FFT-4096, paired-real (8 channels as 4 complex cols), radix-4.
// ============================================================================
__global__ __launch_bounds__(FFT_THREADS, 1) void fft_n_fwd(const float* __restrict__ x) {
    extern __shared__ float2 smc[];
    float2* tw = smc + 4 * N_DIM;
    const int b  = blockIdx.x / 96;
    const int c0 = (blockIdx.x % 96) * 8;
    const int tid = threadIdx.x;

    for (int n = tid; n < N_DIM; n += FFT_THREADS) {
        const float* row = &x[((size_t)(b * N_DIM + n)) * C_DIM + c0];
        float4 v0 = *(const float4*)row;
        float4 v1 = *(const float4*)(row + 4);
        int r = rev4((unsigned)n);
        smc[0 * N_DIM + r] = make_float2(v0.x, v0.y);
        smc[1 * N_DIM + r] = make_float2(v0.z, v0.w);
        smc[2 * N_DIM + r] = make_float2(v1.x, v1.y);
        smc[3 * N_DIM + r] = make_float2(v1.z, v1.w);
    }
    fft4_core<-1>(smc, tw, tid);

    for (int k = tid; k < N_DIM; k += FFT_THREADS) {
        const int kr = (N_DIM - k) & (N_DIM - 1);
        float fr[8], fi[8];
        #pragma unroll
        for (int t = 0; t < 4; t++) {
            float2 P = smc[t * N_DIM + k];
            float2 Q = smc[t * N_DIM + kr];
            fr[2 * t]     = 0.5f * (P.x + Q.x);
            fi[2 * t]     = 0.5f * (P.y - Q.y);
            fr[2 * t + 1] = 0.5f * (P.y + Q.y);
            fi[2 * t + 1] = 0.5f * (Q.x - P.x);
        }
        size_t o = ((size_t)(b * N_DIM + k)) * C_DIM + c0;
        *(float4*)&g_Fr[o]     = *(float4*)&fr[0];
        *(float4*)&g_Fr[o + 4] = *(float4*)&fr[4];
        *(float4*)&g_Fi[o]     = *(float4*)&fi[0];
        *(float4*)&g_Fi[o + 4] = *(float4*)&fi[4];
    }
}

// ============================================================================
// K2: FFT-4 along block axis + 1/128 scale, pack bf16 hi/lo GEMM rows.
// ============================================================================
__global__ void fft4_pack() {
    int idx = blockIdx.x * blockDim.x + threadIdx.x;
    if (idx >= M_TOT * BS) return;
    const int m = idx / BS;
    const int d = idx % BS;

    const size_t base = (size_t)m * C_DIM + d;
    float xr0 = g_Fr[base],          xi0 = g_Fi[base];
    float xr1 = g_Fr[base + BS],     xi1 = g_Fi[base + BS];
    float xr2 = g_Fr[base + 2 * BS], xi2 = g_Fi[base + 2 * BS];
    float xr3 = g_Fr[base + 3 * BS], xi3 = g_Fi[base + 3 * BS];

    float yr[4], yi[4];
    yr[0] = (xr0 + xr1 + xr2 + xr3) * INV128;  yi[0] = (xi0 + xi1 + xi2 + xi3) * INV128;
    yr[1] = (xr0 + xi1 - xr2 - xi3) * INV128;  yi[1] = (xi0 - xr1 - xi2 + xr3) * INV128;
    yr[2] = (xr0 - xr1 + xr2 - xr3) * INV128;  yi[2] = (xi0 - xi1 + xi2 - xi3) * INV128;
    yr[3] = (xr0 - xi1 - xr2 + xi3) * INV128;  yi[3] = (xi0 + xr1 - xi2 - xr3) * INV128;

    const size_t PLX = (size_t)M_TOT * GK;
    #pragma unroll
    for (int p = 0; p < 4; p++) {
        unsigned short* row = g_Xb + p * PLX + (size_t)m * GK;
        __nv_bfloat16 hr = __float2bfloat16(yr[p]);
        __nv_bfloat16 hi = __float2bfloat16(yi[p]);
        row[d]            = __bfloat16_as_ushort(hr);
        row[BS + d]       = __bfloat16_as_ushort(hi);
        row[KS + d]       = __bfloat16_as_ushort(__float2bfloat16(yr[p] - __bfloat162float(hr)));
        row[KS + BS + d]  = __bfloat16_as_ushort(__float2bfloat16(yi[p] - __bfloat162float(hi)));
    }
}

// ============================================================================
// K3: stacked weights, transposed + bf16 hi/lo.  Ws = [[Wr, Wi], [-Wi, Wr]]
// ============================================================================
__global__ void prep_weights(const float* __restrict__ w1, const float* __restrict__ b1,
                             const float* __restrict__ w2, const float* __restrict__ b2) {
    int idx = blockIdx.x * blockDim.x + threadIdx.x;
    if (idx < NB * KS * GK) {
        int k   = idx % GK;
        int n   = (idx / GK) % KS;
        int blk = idx / (GK * KS);
        int kk  = (k >= KS) ? k - KS : k;
        bool lohalf = (k >= KS);
        int dd = (kk < BS) ? kk : kk - BS;
        int cc = (n  < BS) ? n  : n  - BS;
        bool rlo = kk < BS, clo = n < BS;
        size_t ir = ((size_t)blk        * BS + dd) * BS + cc;
        size_t ii = ((size_t)(NB + blk) * BS + dd) * BS + cc;
        float v1, v2;
        if (rlo == clo) { v1 =  w1[ir]; v2 =  w2[ir]; }
        else if (rlo)   { v1 =  w1[ii]; v2 =  w2[ii]; }
        else            { v1 = -w1[ii]; v2 = -w2[ii]; }
        __nv_bfloat16 h1 = __float2bfloat16(v1);
        __nv_bfloat16 h2 = __float2bfloat16(v2);
        if (lohalf) {
            g_W1b[idx] = __bfloat16_as_ushort(__float2bfloat16(v1 - __bfloat162float(h1)));
            g_W2b[idx] = __bfloat16_as_ushort(__float2bfloat16(v2 - __bfloat162float(h2)));
        } else {
            g_W1b[idx] = __bfloat16_as_ushort(h1);
            g_W2b[idx] = __bfloat16_as_ushort(h2);
        }
    }
    if (idx < NB * KS) {
        int blk = idx / KS;
        int c   = idx % KS;
        size_t ib = (c < BS) ? ((size_t)blk * BS + c)
                             : ((size_t)(NB + blk) * BS + (c - BS));
        g_B1[idx] = b1[ib];
        g_B2[idx] = b2[ib];
    }
}

// ============================================================================
// K4/K5: HMMA bf16x3 GEMM. CTA 128x128, 8 warps (4x2), warp tile 32x64.
// 3-stage cp.async pipeline, 2 CTAs/SM.
// ============================================================================
template <int LAYER>
__global__ __launch_bounds__(256, 2) void gemm_mma() {
    extern __shared__ __align__(1024) char smem_raw[];
    const uint32_t smem = smem_u32(smem_raw);
    const int tid    = threadIdx.x;
    const int wid    = tid >> 5;
    const int lane   = tid & 31;
    const int warp_m = wid & 3;
    const int warp_n = wid >> 2;
    const int n0     = blockIdx.x * 128;
    const int tile_m = blockIdx.y * 128;
    const int blk    = blockIdx.z;

    const unsigned short* A = (LAYER == 1 ? g_Xb : g_Hb)
                            + (size_t)blk * M_TOT * GK + (size_t)tile_m * GK;
    const unsigned short* W = (LAYER == 1 ? g_W1b : g_W2b)
                            + (size_t)blk * KS * GK + (size_t)n0 * GK;
    const float* bias       = (LAYER == 1 ? g_B1 : g_B2) + blk * KS;

    float acc[2][8][4];
    #pragma unroll
    for (int i = 0; i < 2; i++)
        #pragma unroll
        for (int j = 0; j < 8; j++)
            #pragma unroll
            for (int q = 0; q < 4; q++) acc[i][j][q] = 0.f;

    #pragma unroll
    for (int c = 0; c < 2; c++) {
        int ao, bo; chunk_offsets(c, ao, bo);
        uint32_t sA = smem + c * STAGE_BYTES;
        load_chunk(A, W, sA, sA + 16384, ao, bo, tid);
    }

    const uint32_t a_row = (uint32_t)(warp_m * 32 + (lane & 15));
    const uint32_t a_cb  = (uint32_t)((lane >> 4) * 16);
    const uint32_t b_row = (uint32_t)(warp_n * 64 + (lane & 7) + ((lane >> 4) * 8));
    const uint32_t b_cb  = (uint32_t)(((lane >> 3) & 1) * 16);

    for (int c = 0; c < KCH; c++) {
        if (c + 1 < KCH) asm volatile("cp.async.wait_group 1;" ::: "memory");
        else             asm volatile("cp.async.wait_group 0;" ::: "memory");
        __syncthreads();

        if (c + 2 < KCH) {
            int ao, bo; chunk_offsets(c + 2, ao, bo);
            uint32_t sL = smem + ((c + 2) % NSTG) * STAGE_BYTES;
            load_chunk(A, W, sL, sL + 16384, ao, bo, tid);
        }

        const uint32_t sA = smem + (c % NSTG) * STAGE_BYTES;
        const uint32_t sB = sA + 16384;

        #pragma unroll
        for (int k16 = 0; k16 < 4; k16++) {
            uint32_t af[2][4], bf[4][4];
            #pragma unroll
            for (int mi = 0; mi < 2; mi++)
                ldsm_x4(af[mi], sA + swz128((a_row + mi * 16) * 128 + k16 * 32 + a_cb));
            #pragma unroll
            for (int nj = 0; nj < 4; nj++)
                ldsm_x4(bf[nj], sB + swz128((b_row + nj * 16) * 128 + k16 * 32 + b_cb));
            #pragma unroll
            for (int mi = 0; mi < 2; mi++)
                #pragma unroll
                for (int nj = 0; nj < 4; nj++) {
                    mma16816(acc[mi][2 * nj],     af[mi], bf[nj][0], bf[nj][1]);
                    mma16816(acc[mi][2 * nj + 1], af[mi], bf[nj][2], bf[nj][3]);
                }
        }
    }

    // epilogue
    #pragma unroll
    for (int mi = 0; mi < 2; mi++) {
        #pragma unroll
        for (int na = 0; na < 8; na++) {
            const int col  = n0 + warp_n * 64 + na * 8 + 2 * (lane & 3);
            const int row0 = tile_m + warp_m * 32 + mi * 16 + (lane >> 2);
            const float b0 = bias[col], b1 = bias[col + 1];
            #pragma unroll
            for (int h = 0; h < 2; h++) {
                const int row = row0 + h * 8;
                float v0 = acc[mi][na][2 * h]     + b0;
                float v1 = acc[mi][na][2 * h + 1] + b1;
                if (LAYER == 1) {
                    v0 = fmaxf(v0, 0.f);
                    v1 = fmaxf(v1, 0.f);
                    __nv_bfloat16 h0 = __float2bfloat16(v0);
                    __nv_bfloat16 h1 = __float2bfloat16(v1);
                    ushort2 hs = make_ushort2(__bfloat16_as_ushort(h0),
                                              __bfloat16_as_ushort(h1));
                    ushort2 ls = make_ushort2(
                        __bfloat16_as_ushort(__float2bfloat16(v0 - __bfloat162float(h0))),
                        __bfloat16_as_ushort(__float2bfloat16(v1 - __bfloat162float(h1))));
                    unsigned short* rb = g_Hb + ((size_t)blk * M_TOT + row) * GK;
                    *(ushort2*)(rb + col)      = hs;
                    *(ushort2*)(rb + KS + col) = ls;
                } else {
                    v0 = (v0 > LAMBDA) ? v0 - LAMBDA
                                       : ((v0 < -LAMBDA) ? v0 + LAMBDA : 0.f);
                    v1 = (v1 > LAMBDA) ? v1 - LAMBDA
                                       : ((v1 < -LAMBDA) ? v1 + LAMBDA : 0.f);
                    *(float2*)(g_P + ((size_t)blk * M_TOT + row) * KS + col)
                        = make_float2(v0, v1);
                }
            }
        }
    }
}

// ============================================================================
// K6: inverse FFT-4 along block axis + hermitian channel-pair packing.
// ============================================================================
__global__ void ifft4_wpack() {
    const int idx = blockIdx.x * blockDim.x + threadIdx.x;
    const int total = B_DIM * 2049 * 96;
    if (idx >= total) return;
    const int dp   = idx % 96;
    const int kpos = (idx / 96) % 2049;
    const int b    = idx / (96 * 2049);
    const int d    = 2 * dp;
    const int m1   = b * N_DIM + kpos;
    const int m2   = b * N_DIM + ((N_DIM - kpos) & (N_DIM - 1));

    const size_t PL = (size_t)M_TOT * KS;

    float z1r[4], z1i[4], z2r[4], z2i[4];
    #pragma unroll
    for (int rowsel = 0; rowsel < 2; rowsel++) {
        const int m = rowsel ? m2 : m1;
        float yrA[4], yiA[4], yrB[4], yiB[4];
        #pragma unroll
        for (int k2 = 0; k2 < 4; k2++) {
            const float* pp = g_P + k2 * PL + (size_t)m * KS;
            float2 re = *(const float2*)(pp + d);
            float2 im = *(const float2*)(pp + BS + d);
            yrA[k2] = re.x;  yrB[k2] = re.y;
            yiA[k2] = im.x;  yiB[k2] = im.y;
        }
        float zrA[4], ziA[4], zrB[4], ziB[4];
        zrA[0] = yrA[0] + yrA[1] + yrA[2] + yrA[3];
        ziA[0] = yiA[0] + yiA[1] + yiA[2] + yiA[3];
        zrA[1] = yrA[0] - yiA[1] - yrA[2] + yiA[3];
        ziA[1] = yiA[0] + yrA[1] - yiA[2] - yrA[3];
        zrA[2] = yrA[0] - yrA[1] + yrA[2] - yrA[3];
        ziA[2] = yiA[0] - yiA[1] + yiA[2] - yiA[3];
        zrA[3] = yrA[0] + yiA[1] - yrA[2] - yiA[3];
        ziA[3] = yiA[0] - yrA[1] - yiA[2] + yrA[3];
        zrB[0] = yrB[0] + yrB[1] + yrB[2] + yrB[3];
        ziB[0] = yiB[0] + yiB[1] + yiB[2] + yiB[3];
        zrB[1] = yrB[0] - yiB[1] - yrB[2] + yiB[3];
        ziB[1] = yiB[0] + yrB[1] - yiB[2] - yrB[3];
        zrB[2] = yrB[0] - yrB[1] + yrB[2] - yrB[3];
        ziB[2] = yiB[0] - yiB[1] + yiB[2] - yiB[3];
        zrB[3] = yrB[0] + yiB[1] - yrB[2] - yiB[3];
        ziB[3] = yiB[0] - yrB[1] - yiB[2] + yrB[3];
        if (rowsel == 0) {
            #pragma unroll
            for (int j = 0; j < 4; j++) {
                z1r[j] = zrA[j]; z1i[j] = ziA[j];
                z2r[j] = zrB[j]; z2i[j] = ziB[j];
            }
        } else {
            #pragma unroll
            for (int j = 0; j < 4; j++) {
                float v1r = 0.5f * (z1r[j] + zrA[j]);
                float v1i = 0.5f * (z1i[j] - ziA[j]);
                float v2r = 0.5f * (z2r[j] + zrB[j]);
                float v2i = 0.5f * (z2i[j] - ziB[j]);
                g_Wc[((size_t)j * M_TOT + m1) * 96 + dp] =
                    make_float2(v1r - v2i, v1i + v2r);
                g_Wc[((size_t)j * M_TOT + m2) * 96 + dp] =
                    make_float2(v1r + v2i, -v1i + v2r);
            }
        }
    }
}

// ============================================================================
// K7: inverse FFT-4096 on packed hermitian columns (radix-4); outputs real.
// ============================================================================
__global__ __launch_bounds__(FFT_THREADS, 1) void fft_n_inv(float* __restrict__ out) {
    extern __shared__ float2 smc[];
    float2* tw = smc + 4 * N_DIM;
    const int b   = blockIdx.x / 96;
    const int r8  = blockIdx.x % 96;
    const int blk = r8 / 24;
    const int dp0 = (r8 % 24) * 4;
    const int tid = threadIdx.x;

    for (int k = tid; k < N_DIM; k += FFT_THREADS) {
        const float2* wp = g_Wc + ((size_t)blk * M_TOT + b * N_DIM + k) * 96 + dp0;
        float2 w0 = wp[0], w1 = wp[1], w2 = wp[2], w3 = wp[3];
        int r = rev4((unsigned)k);
        smc[0 * N_DIM + r] = w0;
        smc[1 * N_DIM + r] = w1;
        smc[2 * N_DIM + r] = w2;
        smc[3 * N_DIM + r] = w3;
    }
    fft4_core<+1>(smc, tw, tid);

    const int cbase = blk * BS + 2 * dp0;
    for (int n = tid; n < N_DIM; n += FFT_THREADS) {
        float2 c0 = smc[n],             c1 = smc[N_DIM + n];
        float2 c2 = smc[2 * N_DIM + n], c3 = smc[3 * N_DIM + n];
        float4 o0 = make_float4(c0.x * INV128, c0.y * INV128,
                                c1.x * INV128, c1.y * INV128);
        float4 o1 = make_float4(c2.x * INV128, c2.y * INV128,
                                c3.x * INV128, c3.y * INV128);
        float* op = &out[((size_t)(b * N_DIM + n)) * C_DIM + cbase];
        *(float4*)op       = o0;
        *(float4*)(op + 4) = o1;
    }
}

// ============================================================================
// launch
// ============================================================================
extern "C" void kernel_launch(void* const* d_in, const int* in_sizes, int n_in,
                              void* d_out, int out_size) {
    (void)in_sizes; (void)n_in; (void)out_size;
    const float* x  = (const float*)d_in[0];
    const float* w1 = (const float*)d_in[1];
    const float* b1 = (const float*)d_in[2];
    const float* w2 = (const float*)d_in[3];
    const float* b2 = (const float*)d_in[4];
    float* out = (float*)d_out;

    cudaFuncSetAttribute(fft_n_fwd, cudaFuncAttributeMaxDynamicSharedMemorySize, FFT_SMEM);
    cudaFuncSetAttribute(fft_n_inv, cudaFuncAttributeMaxDynamicSharedMemorySize, FFT_SMEM);
    cudaFuncSetAttribute(gemm_mma<1>, cudaFuncAttributeMaxDynamicSharedMemorySize, GEMM_SMEM);
    cudaFuncSetAttribute(gemm_mma<2>, cudaFuncAttributeMaxDynamicSharedMemorySize, GEMM_SMEM);

    fft_n_fwd<<<B_DIM * 96, FFT_THREADS, FFT_SMEM>>>(x);
    fft4_pack<<<(M_TOT * BS) / 256, 256>>>();
    prep_weights<<<(NB * KS * GK + 255) / 256, 256>>>(w1, b1, w2, b2);

    dim3 gg(3, M_TOT / 128, NB);
    gemm_mma<1><<<gg, 256, GEMM_SMEM>>>();
    gemm_mma<2><<<gg, 256, GEMM_SMEM>>>();

    ifft4_wpack<<<(B_DIM * 2049 * 96 + 255) / 256, 256>>>();
    fft_n_inv<<<B_DIM * 96, FFT_THREADS, FFT_SMEM>>>(out);
}